// round 2
// baseline (speedup 1.0000x reference)
#include <cuda_runtime.h>
#include <cuda_bf16.h>
#include <math.h>

// Problem constants
#define BB   64
#define TT   32
#define TMAX 31
#define FF   512
#define LL   196
#define EE   512
#define HH   512
#define AA   512
#define VV   10000

#define FL   (FF*LL)        // 100352
#define ENATT_M (BB*LL)     // 12544

// -------------------- scratch (static device globals; no allocs) ------------
__device__ float g_enatt[BB*LL*AA];      // 25.7 MB
__device__ float g_meanf[BB*FF];
__device__ float g_h[BB*HH];
__device__ float g_c[BB*HH];
__device__ float g_defb[BB*1024];        // [b][0:512]=de, [512:1024]=fbeta pre-act
__device__ float g_x[BB*1024];           // [emb | z]
__device__ float g_gates[BB*4*HH];
__device__ float g_Hs[TMAX*BB*HH];       // h_new per step (pre-mask)
__device__ float g_Wdf[1024*512];        // [W_dec ; W_fbeta]
__device__ float g_bdf[1024];

// -------------------- helpers ----------------------------------------------
__device__ __forceinline__ float sigm(float v) { return 1.f/(1.f+expf(-v)); }

// -------------------- setup: concat W_dec/W_fbeta ---------------------------
__global__ void setup_wdf(const float* __restrict__ W_dec, const float* __restrict__ b_dec,
                          const float* __restrict__ W_fb,  const float* __restrict__ b_fb) {
    int i = blockIdx.x*blockDim.x + threadIdx.x;
    if (i < 512*512) { g_Wdf[i] = W_dec[i]; g_Wdf[512*512 + i] = W_fb[i]; }
    if (i < 512)     { g_bdf[i] = b_dec[i]; g_bdf[512 + i] = b_fb[i]; }
}

// -------------------- mean over L (raw [B,F,L] layout) ----------------------
__global__ void mean_kernel(const float* __restrict__ features) {
    int gw   = (blockIdx.x*blockDim.x + threadIdx.x) >> 5;
    int lane = threadIdx.x & 31;
    if (gw >= BB*FF) return;
    int b = gw >> 9, f = gw & 511;
    const float* p = features + (size_t)b*FL + (size_t)f*LL;
    float s = 0.f;
    for (int l = lane; l < LL; l += 32) s += p[l];
    #pragma unroll
    for (int o = 16; o; o >>= 1) s += __shfl_xor_sync(0xffffffffu, s, o);
    if (lane == 0) g_meanf[gw] = s * (1.f/196.f);
}

// -------------------- generic NT GEMM: C[m,n] = sum_k A[m,k]*B[n,k] + bias[n]
#define BM 64
#define BN 64
#define BK 16
__global__ __launch_bounds__(256)
void gemm_nt_bias(const float* __restrict__ A, const float* __restrict__ Bm,
                  const float* __restrict__ bias, float* __restrict__ C,
                  int M, int N, int K) {
    __shared__ float As[BM][BK+1];
    __shared__ float Bs[BN][BK+1];
    int bm = blockIdx.y * BM, bn = blockIdx.x * BN;
    int tid = threadIdx.x;
    int lr = tid >> 2, lk = (tid & 3) * 4;
    int rm = (tid & 15) * 4, rn = (tid >> 4) * 4;
    float acc[4][4] = {};
    for (int k0 = 0; k0 < K; k0 += BK) {
        float4 av = make_float4(0,0,0,0), bv = make_float4(0,0,0,0);
        int arow = bm + lr, brow = bn + lr;
        if (arow < M) av = *reinterpret_cast<const float4*>(A + (size_t)arow*K + k0 + lk);
        if (brow < N) bv = *reinterpret_cast<const float4*>(Bm + (size_t)brow*K + k0 + lk);
        As[lr][lk+0]=av.x; As[lr][lk+1]=av.y; As[lr][lk+2]=av.z; As[lr][lk+3]=av.w;
        Bs[lr][lk+0]=bv.x; Bs[lr][lk+1]=bv.y; Bs[lr][lk+2]=bv.z; Bs[lr][lk+3]=bv.w;
        __syncthreads();
        #pragma unroll
        for (int kk = 0; kk < BK; kk++) {
            float a[4], bb[4];
            #pragma unroll
            for (int i = 0; i < 4; i++) a[i]  = As[rm+i][kk];
            #pragma unroll
            for (int j = 0; j < 4; j++) bb[j] = Bs[rn+j][kk];
            #pragma unroll
            for (int i = 0; i < 4; i++)
                #pragma unroll
                for (int j = 0; j < 4; j++)
                    acc[i][j] = fmaf(a[i], bb[j], acc[i][j]);
        }
        __syncthreads();
    }
    #pragma unroll
    for (int i = 0; i < 4; i++) {
        int m = bm + rm + i;
        if (m >= M) continue;
        #pragma unroll
        for (int j = 0; j < 4; j++) {
            int n = bn + rn + j;
            if (n < N) C[(size_t)m*N + n] = acc[i][j] + (bias ? bias[n] : 0.f);
        }
    }
}

// -------------------- gates GEMM: [64,2048] = x@W_ih^T + h@W_hh^T + b -------
__global__ __launch_bounds__(256)
void gemm_gates(const float* __restrict__ W_ih, const float* __restrict__ W_hh,
                const float* __restrict__ b_ih, const float* __restrict__ b_hh) {
    __shared__ float As[BM][BK+1];
    __shared__ float Bs[BN][BK+1];
    int bn = blockIdx.x * BN;
    int tid = threadIdx.x;
    int lr = tid >> 2, lk = (tid & 3) * 4;
    int rm = (tid & 15) * 4, rn = (tid >> 4) * 4;
    float acc[4][4] = {};
    // phase 1: x (K=1024) with W_ih ; phase 2: h (K=512) with W_hh
    for (int phase = 0; phase < 2; phase++) {
        const float* A  = phase ? g_h : g_x;
        const float* Bm = phase ? W_hh : W_ih;
        int K = phase ? 512 : 1024;
        for (int k0 = 0; k0 < K; k0 += BK) {
            float4 av = *reinterpret_cast<const float4*>(A + (size_t)lr*K + k0 + lk);
            float4 bv = *reinterpret_cast<const float4*>(Bm + (size_t)(bn+lr)*K + k0 + lk);
            As[lr][lk+0]=av.x; As[lr][lk+1]=av.y; As[lr][lk+2]=av.z; As[lr][lk+3]=av.w;
            Bs[lr][lk+0]=bv.x; Bs[lr][lk+1]=bv.y; Bs[lr][lk+2]=bv.z; Bs[lr][lk+3]=bv.w;
            __syncthreads();
            #pragma unroll
            for (int kk = 0; kk < BK; kk++) {
                float a[4], bb[4];
                #pragma unroll
                for (int i = 0; i < 4; i++) a[i]  = As[rm+i][kk];
                #pragma unroll
                for (int j = 0; j < 4; j++) bb[j] = Bs[rn+j][kk];
                #pragma unroll
                for (int i = 0; i < 4; i++)
                    #pragma unroll
                    for (int j = 0; j < 4; j++)
                        acc[i][j] = fmaf(a[i], bb[j], acc[i][j]);
            }
            __syncthreads();
        }
    }
    #pragma unroll
    for (int i = 0; i < 4; i++) {
        int m = rm + i;
        #pragma unroll
        for (int j = 0; j < 4; j++) {
            int n = bn + rn + j;
            g_gates[(size_t)m*2048 + n] = acc[i][j] + b_ih[n] + b_hh[n];
        }
    }
}

// -------------------- attention step (one block per batch elem) -------------
__global__ __launch_bounds__(256)
void attention_step(const float* __restrict__ features,
                    const float* __restrict__ W_full,
                    const float* __restrict__ W_emb,
                    const int*   __restrict__ captions,
                    const int*   __restrict__ lengths,
                    float* __restrict__ alphas_out, int t) {
    int b    = blockIdx.x;
    int tid  = threadIdx.x;
    int lane = tid & 31, wid = tid >> 5;
    __shared__ float sc[LL];
    __shared__ float de_s[AA];
    __shared__ float wf_s[AA];
    __shared__ float red[8];

    for (int i = tid; i < AA; i += 256) {
        de_s[i] = g_defb[b*1024 + i];
        wf_s[i] = W_full[i];
    }
    __syncthreads();

    // scores: warp per l (strided)
    for (int l = wid; l < LL; l += 8) {
        const float* ea = g_enatt + ((size_t)b*LL + l)*AA;
        float s = 0.f;
        #pragma unroll 4
        for (int a = lane; a < AA; a += 32)
            s += tanhf(ea[a] + de_s[a]) * wf_s[a];
        #pragma unroll
        for (int o = 16; o; o >>= 1) s += __shfl_xor_sync(0xffffffffu, s, o);
        if (lane == 0) sc[l] = s;
    }
    __syncthreads();

    // block max
    float mx = -1e30f;
    for (int l = tid; l < LL; l += 256) mx = fmaxf(mx, sc[l]);
    #pragma unroll
    for (int o = 16; o; o >>= 1) mx = fmaxf(mx, __shfl_xor_sync(0xffffffffu, mx, o));
    if (lane == 0) red[wid] = mx;
    __syncthreads();
    if (wid == 0) {
        float v = (lane < 8) ? red[lane] : -1e30f;
        #pragma unroll
        for (int o = 4; o; o >>= 1) v = fmaxf(v, __shfl_xor_sync(0xffffffffu, v, o));
        if (lane == 0) red[0] = v;
    }
    __syncthreads();
    mx = red[0];
    __syncthreads();

    // exp in place + block sum
    float sum = 0.f;
    for (int l = tid; l < LL; l += 256) {
        float e = expf(sc[l] - mx);
        sc[l] = e;
        sum += e;
    }
    #pragma unroll
    for (int o = 16; o; o >>= 1) sum += __shfl_xor_sync(0xffffffffu, sum, o);
    if (lane == 0) red[wid] = sum;
    __syncthreads();
    if (wid == 0) {
        float v = (lane < 8) ? red[lane] : 0.f;
        #pragma unroll
        for (int o = 4; o; o >>= 1) v += __shfl_xor_sync(0xffffffffu, v, o);
        if (lane == 0) red[0] = v;
    }
    __syncthreads();
    float inv = 1.f / red[0];

    bool active = (lengths[b] - 1) > t;

    // masked alphas out
    for (int l = tid; l < LL; l += 256)
        alphas_out[(size_t)b*(TMAX*LL) + (size_t)t*LL + l] = active ? sc[l]*inv : 0.f;

    // z = (alpha @ feat_r[b]) * sigmoid(fbeta), write into x[:,512:]
    const float* fb_base = features + (size_t)b*FL;
    for (int f = tid; f < FF; f += 256) {
        float z = 0.f;
        #pragma unroll 4
        for (int l = 0; l < LL; l++)
            z = fmaf(sc[l], fb_base[(size_t)l*FF + f], z);
        z *= inv;
        float gate = sigm(g_defb[b*1024 + 512 + f]);
        g_x[b*1024 + 512 + f] = z * gate;
    }

    // embedding into x[:,0:512]
    int cap = captions[b*TT + t];
    for (int e = tid; e < EE; e += 256)
        g_x[b*1024 + e] = W_emb[(size_t)cap*EE + e];
}

// -------------------- LSTM cell update --------------------------------------
__global__ void cell_kernel(const int* __restrict__ lengths, int t) {
    int idx = blockIdx.x*blockDim.x + threadIdx.x;
    if (idx >= BB*HH) return;
    int b = idx >> 9, j = idx & 511;
    const float* g = g_gates + (size_t)b*2048;
    float gi = g[j], gf = g[512+j], gg = g[1024+j], go = g[1536+j];
    float c_old = g_c[idx];
    float cn = sigm(gf)*c_old + sigm(gi)*tanhf(gg);
    float hn = sigm(go)*tanhf(cn);
    g_Hs[(size_t)t*(BB*HH) + idx] = hn;
    if ((lengths[b] - 1) > t) { g_c[idx] = cn; g_h[idx] = hn; }
}

// -------------------- final preds GEMM with ragged mask ---------------------
__global__ __launch_bounds__(256)
void gemm_preds(const float* __restrict__ W_out, const float* __restrict__ b_out,
                const int* __restrict__ lengths, float* __restrict__ out) {
    __shared__ float As[BM][BK+1];
    __shared__ float Bs[BN][BK+1];
    const int N = VV, K = HH;
    int bm = blockIdx.y * BM, bn = blockIdx.x * BN;
    int tid = threadIdx.x;
    int lr = tid >> 2, lk = (tid & 3) * 4;
    int rm = (tid & 15) * 4, rn = (tid >> 4) * 4;
    float acc[4][4] = {};
    for (int k0 = 0; k0 < K; k0 += BK) {
        float4 av = *reinterpret_cast<const float4*>(g_Hs + (size_t)(bm+lr)*K + k0 + lk);
        float4 bv = make_float4(0,0,0,0);
        int brow = bn + lr;
        if (brow < N) bv = *reinterpret_cast<const float4*>(W_out + (size_t)brow*K + k0 + lk);
        As[lr][lk+0]=av.x; As[lr][lk+1]=av.y; As[lr][lk+2]=av.z; As[lr][lk+3]=av.w;
        Bs[lr][lk+0]=bv.x; Bs[lr][lk+1]=bv.y; Bs[lr][lk+2]=bv.z; Bs[lr][lk+3]=bv.w;
        __syncthreads();
        #pragma unroll
        for (int kk = 0; kk < BK; kk++) {
            float a[4], bb[4];
            #pragma unroll
            for (int i = 0; i < 4; i++) a[i]  = As[rm+i][kk];
            #pragma unroll
            for (int j = 0; j < 4; j++) bb[j] = Bs[rn+j][kk];
            #pragma unroll
            for (int i = 0; i < 4; i++)
                #pragma unroll
                for (int j = 0; j < 4; j++)
                    acc[i][j] = fmaf(a[i], bb[j], acc[i][j]);
        }
        __syncthreads();
    }
    #pragma unroll
    for (int i = 0; i < 4; i++) {
        int m = bm + rm + i;          // m = t*64 + b
        int t_ = m >> 6, b_ = m & 63;
        bool act = (lengths[b_] - 1) > t_;
        #pragma unroll
        for (int j = 0; j < 4; j++) {
            int n = bn + rn + j;
            if (n < N)
                out[(size_t)b_*(TMAX*VV) + (size_t)t_*VV + n] =
                    act ? acc[i][j] + b_out[n] : 0.f;
        }
    }
}

// -------------------- host launcher -----------------------------------------
extern "C" void kernel_launch(void* const* d_in, const int* in_sizes, int n_in,
                              void* d_out, int out_size) {
    const float* features = (const float*)d_in[0];
    const int*   captions = (const int*)  d_in[1];
    const int*   lengths  = (const int*)  d_in[2];
    const float* W_emb    = (const float*)d_in[3];
    const float* W_enc    = (const float*)d_in[4];
    const float* b_enc    = (const float*)d_in[5];
    const float* W_dec    = (const float*)d_in[6];
    const float* b_dec    = (const float*)d_in[7];
    const float* W_full   = (const float*)d_in[8];
    /* b_full (d_in[9]) is softmax-invariant: unused */
    const float* W_fbeta  = (const float*)d_in[10];
    const float* b_fbeta  = (const float*)d_in[11];
    const float* W_ih     = (const float*)d_in[12];
    const float* W_hh     = (const float*)d_in[13];
    const float* b_ih     = (const float*)d_in[14];
    const float* b_hh     = (const float*)d_in[15];
    const float* W_out    = (const float*)d_in[16];
    const float* b_out    = (const float*)d_in[17];
    const float* W_init_h = (const float*)d_in[18];
    const float* b_init_h = (const float*)d_in[19];
    const float* W_init_c = (const float*)d_in[20];
    const float* b_init_c = (const float*)d_in[21];

    float* out = (float*)d_out;
    float* alphas_out = out + (size_t)BB*TMAX*VV;   // preds first, alphas after

    (void)n_in; (void)in_sizes; (void)out_size;

    // CRITICAL: get DEVICE addresses of __device__ globals. Passing the symbol
    // directly from host code passes the host shadow address (which GB300's
    // ATS happily dereferences into host memory -> silent corruption).
    float *p_enatt, *p_meanf, *p_h, *p_c, *p_defb, *p_Wdf, *p_bdf;
    cudaGetSymbolAddress((void**)&p_enatt, g_enatt);
    cudaGetSymbolAddress((void**)&p_meanf, g_meanf);
    cudaGetSymbolAddress((void**)&p_h,     g_h);
    cudaGetSymbolAddress((void**)&p_c,     g_c);
    cudaGetSymbolAddress((void**)&p_defb,  g_defb);
    cudaGetSymbolAddress((void**)&p_Wdf,   g_Wdf);
    cudaGetSymbolAddress((void**)&p_bdf,   g_bdf);

    // setup: concat W_dec/W_fbeta
    setup_wdf<<<(512*512 + 255)/256, 256>>>(W_dec, b_dec, W_fbeta, b_fbeta);

    // en_att = feat_r @ W_enc^T + b_enc   (M=12544, N=512, K=512)
    {
        dim3 g(AA/BN, ENATT_M/BM);
        gemm_nt_bias<<<g, 256>>>(features, W_enc, b_enc, p_enatt, ENATT_M, AA, FF);
    }

    // mean over L, then h0/c0
    mean_kernel<<<(BB*FF*32 + 255)/256, 256>>>(features);
    {
        dim3 g(HH/BN, 1);
        gemm_nt_bias<<<g, 256>>>(p_meanf, W_init_h, b_init_h, p_h, BB, HH, FF);
        gemm_nt_bias<<<g, 256>>>(p_meanf, W_init_c, b_init_c, p_c, BB, HH, FF);
    }

    // recurrence
    for (int t = 0; t < TMAX; t++) {
        // de & fbeta pre-act in one GEMM: [64,1024] = h @ [W_dec;W_fbeta]^T
        dim3 gp(1024/BN, 1);
        gemm_nt_bias<<<gp, 256>>>(p_h, p_Wdf, p_bdf, p_defb, BB, 1024, HH);

        attention_step<<<BB, 256>>>(features, W_full, W_emb, captions, lengths,
                                    alphas_out, t);

        gemm_gates<<<2048/BN, 256>>>(W_ih, W_hh, b_ih, b_hh);

        cell_kernel<<<(BB*HH + 255)/256, 256>>>(lengths, t);
    }

    // final output projection with ragged mask (M=1984, N=10000, K=512)
    {
        dim3 g((VV + BN - 1)/BN, (TMAX*BB)/BM);
        gemm_preds<<<g, 256>>>(W_out, b_out, lengths, out);
    }
}

// round 3
// speedup vs baseline: 1.1076x; 1.1076x over previous
#include <cuda_runtime.h>
#include <cuda_bf16.h>
#include <math.h>

// Problem constants
#define BB   64
#define TT   32
#define TMAX 31
#define FF   512
#define LL   196
#define EE   512
#define HH   512
#define AA   512
#define VV   10000

#define FL   (FF*LL)        // 100352
#define ENATT_M (BB*LL)     // 12544

// -------------------- scratch (static device globals; no allocs) ------------
__device__ float g_enatt[BB*LL*AA];        // 25.7 MB
__device__ float g_meanf[BB*FF];
__device__ float g_hc[2][BB*1024];         // double-buffered [h | c] per b, parity = t&1
__device__ float g_x[BB*1024];             // [emb | z]
__device__ float g_Hs[TMAX*BB*HH];         // h_new per step (pre-mask), row m=t*64+b
__device__ float g_WdfT[512*1024];         // transposed concat [W_dec; W_fbeta]: [k][j]
__device__ float g_bdf[1024];
__device__ float g_Winit[1024*512];        // concat [W_init_h; W_init_c]
__device__ float g_binit[1024];
__device__ int   g_rowmap[TMAX*BB];
__device__ int   g_count;

__device__ __forceinline__ float sigm(float v) { return 1.f/(1.f+expf(-v)); }

// -------------------- setup: transposes / concats ---------------------------
__global__ void setup_all(const float* __restrict__ W_dec, const float* __restrict__ b_dec,
                          const float* __restrict__ W_fb,  const float* __restrict__ b_fb,
                          const float* __restrict__ W_ih_, const float* __restrict__ b_ih_,
                          const float* __restrict__ W_ic_, const float* __restrict__ b_ic_) {
    int i = blockIdx.x*blockDim.x + threadIdx.x;      // 0 .. 524287
    int j = i >> 9, k = i & 511;                      // j: 0..1023
    float v = (j < 512) ? W_dec[j*512 + k] : W_fb[(j-512)*512 + k];
    g_WdfT[k*1024 + j] = v;
    g_Winit[(size_t)j*512 + k] = (j < 512) ? W_ih_[j*512 + k] : W_ic_[(j-512)*512 + k];
    if (i < 1024) {
        g_bdf[i]   = (i < 512) ? b_dec[i] : b_fb[i-512];
        g_binit[i] = (i < 512) ? b_ih_[i] : b_ic_[i-512];
    }
}

// -------------------- row compaction for ragged preds -----------------------
__global__ void setup_rowmap(const int* __restrict__ lengths) {
    __shared__ int nt[TMAX+1];
    int tid = threadIdx.x;
    if (tid < TMAX) {
        int n = 0;
        for (int b = 0; b < BB; b++) n += (lengths[b]-1 > tid);
        nt[tid] = n;
    }
    __syncthreads();
    if (tid == 0) {
        int pre = 0;
        for (int t = 0; t < TMAX; t++) { int n = nt[t]; nt[t] = pre; pre += n; }
        nt[TMAX] = pre;
        g_count = pre;
    }
    __syncthreads();
    for (int t = 0; t < TMAX; t++) {
        int base = nt[t];
        int cnt  = nt[t+1] - base;
        for (int b = tid; b < cnt; b += blockDim.x)
            g_rowmap[base + b] = t*64 + b;   // lengths sorted desc -> active b's are a prefix
    }
}

__global__ void zero_inactive(const int* __restrict__ lengths, float* __restrict__ out) {
    int m = blockIdx.x;           // 0..1983
    int t = m >> 6, b = m & 63;
    if (lengths[b]-1 > t) return;
    float4* p = reinterpret_cast<float4*>(out + (size_t)b*(TMAX*VV) + (size_t)t*VV);
    float4 z = make_float4(0,0,0,0);
    for (int i = threadIdx.x; i < VV/4; i += blockDim.x) p[i] = z;
}

// -------------------- mean over L (raw [B,F,L] layout) ----------------------
__global__ void mean_kernel(const float* __restrict__ features) {
    int gw   = (blockIdx.x*blockDim.x + threadIdx.x) >> 5;
    int lane = threadIdx.x & 31;
    if (gw >= BB*FF) return;
    int b = gw >> 9, f = gw & 511;
    const float* p = features + (size_t)b*FL + (size_t)f*LL;
    float s = 0.f;
    for (int l = lane; l < LL; l += 32) s += p[l];
    #pragma unroll
    for (int o = 16; o; o >>= 1) s += __shfl_xor_sync(0xffffffffu, s, o);
    if (lane == 0) g_meanf[gw] = s * (1.f/196.f);
}

// -------------------- small NT GEMM (used once for h0/c0 init) --------------
#define BM 64
#define BN 64
#define BK 16
__global__ __launch_bounds__(256)
void gemm_nt_bias(const float* __restrict__ A, const float* __restrict__ Bm,
                  const float* __restrict__ bias, float* __restrict__ C,
                  int M, int N, int K) {
    __shared__ float As[BM][BK+1];
    __shared__ float Bs[BN][BK+1];
    int bm = blockIdx.y * BM, bn = blockIdx.x * BN;
    int tid = threadIdx.x;
    int lr = tid >> 2, lk = (tid & 3) * 4;
    int rm = (tid & 15) * 4, rn = (tid >> 4) * 4;
    float acc[4][4] = {};
    for (int k0 = 0; k0 < K; k0 += BK) {
        float4 av = make_float4(0,0,0,0), bv = make_float4(0,0,0,0);
        int arow = bm + lr, brow = bn + lr;
        if (arow < M) av = *reinterpret_cast<const float4*>(A + (size_t)arow*K + k0 + lk);
        if (brow < N) bv = *reinterpret_cast<const float4*>(Bm + (size_t)brow*K + k0 + lk);
        As[lr][lk+0]=av.x; As[lr][lk+1]=av.y; As[lr][lk+2]=av.z; As[lr][lk+3]=av.w;
        Bs[lr][lk+0]=bv.x; Bs[lr][lk+1]=bv.y; Bs[lr][lk+2]=bv.z; Bs[lr][lk+3]=bv.w;
        __syncthreads();
        #pragma unroll
        for (int kk = 0; kk < BK; kk++) {
            float a[4], bb[4];
            #pragma unroll
            for (int i = 0; i < 4; i++) a[i]  = As[rm+i][kk];
            #pragma unroll
            for (int j = 0; j < 4; j++) bb[j] = Bs[rn+j][kk];
            #pragma unroll
            for (int i = 0; i < 4; i++)
                #pragma unroll
                for (int j = 0; j < 4; j++)
                    acc[i][j] = fmaf(a[i], bb[j], acc[i][j]);
        }
        __syncthreads();
    }
    #pragma unroll
    for (int i = 0; i < 4; i++) {
        int m = bm + rm + i;
        if (m >= M) continue;
        #pragma unroll
        for (int j = 0; j < 4; j++) {
            int n = bn + rn + j;
            if (n < N) C[(size_t)m*N + n] = acc[i][j] + (bias ? bias[n] : 0.f);
        }
    }
}

// -------------------- big double-buffered SGEMM 128x128x8 -------------------
#define GBM 128
#define GBN 128
#define GBK 8
__global__ __launch_bounds__(256, 2)
void gemm128(const float* __restrict__ A, const float* __restrict__ B,
             const float* __restrict__ bias, float* __restrict__ C,
             int M, int N, int K) {
    __shared__ float As[2][GBK][GBM];
    __shared__ float Bs[2][GBK][GBN];
    int bm = blockIdx.y * GBM, bn = blockIdx.x * GBN;
    int tid = threadIdx.x;
    int lrow = tid >> 1;            // 0..127
    int lk   = (tid & 1) * 4;       // 0 or 4
    int tx = tid & 15, ty = tid >> 4;
    int rm = ty*8, rn = tx*8;
    float acc[8][8] = {};
    float4 aR, bR;
    const float4 Z4 = make_float4(0,0,0,0);
    {
        int ar = bm + lrow, br = bn + lrow;
        aR = (ar < M) ? *reinterpret_cast<const float4*>(A + (size_t)ar*K + lk) : Z4;
        bR = (br < N) ? *reinterpret_cast<const float4*>(B + (size_t)br*K + lk) : Z4;
        As[0][lk+0][lrow]=aR.x; As[0][lk+1][lrow]=aR.y; As[0][lk+2][lrow]=aR.z; As[0][lk+3][lrow]=aR.w;
        Bs[0][lk+0][lrow]=bR.x; Bs[0][lk+1][lrow]=bR.y; Bs[0][lk+2][lrow]=bR.z; Bs[0][lk+3][lrow]=bR.w;
    }
    __syncthreads();
    int buf = 0;
    for (int k0 = GBK; k0 <= K; k0 += GBK) {
        bool more = (k0 < K);
        if (more) {
            int ar = bm + lrow, br = bn + lrow;
            aR = (ar < M) ? *reinterpret_cast<const float4*>(A + (size_t)ar*K + k0 + lk) : Z4;
            bR = (br < N) ? *reinterpret_cast<const float4*>(B + (size_t)br*K + k0 + lk) : Z4;
        }
        #pragma unroll
        for (int kk = 0; kk < GBK; kk++) {
            float a[8], b[8];
            *reinterpret_cast<float4*>(a)   = *reinterpret_cast<const float4*>(&As[buf][kk][rm]);
            *reinterpret_cast<float4*>(a+4) = *reinterpret_cast<const float4*>(&As[buf][kk][rm+4]);
            *reinterpret_cast<float4*>(b)   = *reinterpret_cast<const float4*>(&Bs[buf][kk][rn]);
            *reinterpret_cast<float4*>(b+4) = *reinterpret_cast<const float4*>(&Bs[buf][kk][rn+4]);
            #pragma unroll
            for (int i = 0; i < 8; i++)
                #pragma unroll
                for (int j = 0; j < 8; j++)
                    acc[i][j] = fmaf(a[i], b[j], acc[i][j]);
        }
        if (more) {
            int nb = buf ^ 1;
            As[nb][lk+0][lrow]=aR.x; As[nb][lk+1][lrow]=aR.y; As[nb][lk+2][lrow]=aR.z; As[nb][lk+3][lrow]=aR.w;
            Bs[nb][lk+0][lrow]=bR.x; Bs[nb][lk+1][lrow]=bR.y; Bs[nb][lk+2][lrow]=bR.z; Bs[nb][lk+3][lrow]=bR.w;
        }
        __syncthreads();
        buf ^= 1;
    }
    #pragma unroll
    for (int i = 0; i < 8; i++) {
        int m = bm + rm + i;
        if (m >= M) continue;
        float* crow = C + (size_t)m*N;
        #pragma unroll
        for (int j = 0; j < 8; j++) {
            int n = bn + rn + j;
            if (n < N) crow[n] = acc[i][j] + (bias ? bias[n] : 0.f);
        }
    }
}

// ------ preds GEMM on compacted active rows (A rows via g_rowmap -> g_Hs) ---
__global__ __launch_bounds__(256, 2)
void gemm_preds_c(const float* __restrict__ B, const float* __restrict__ bias,
                  float* __restrict__ out) {
    __shared__ float As[2][GBK][GBM];
    __shared__ float Bs[2][GBK][GBN];
    const int N = VV, K = HH;
    int count = g_count;
    int bm = blockIdx.y * GBM, bn = blockIdx.x * GBN;
    if (bm >= count) return;
    int tid = threadIdx.x;
    int lrow = tid >> 1;
    int lk   = (tid & 1) * 4;
    int tx = tid & 15, ty = tid >> 4;
    int rm = ty*8, rn = tx*8;
    float acc[8][8] = {};
    float4 aR, bR;
    const float4 Z4 = make_float4(0,0,0,0);
    int arow_m = (bm + lrow < count) ? g_rowmap[bm + lrow] : -1;
    {
        int br = bn + lrow;
        aR = (arow_m >= 0) ? *reinterpret_cast<const float4*>(g_Hs + (size_t)arow_m*K + lk) : Z4;
        bR = (br < N)      ? *reinterpret_cast<const float4*>(B + (size_t)br*K + lk) : Z4;
        As[0][lk+0][lrow]=aR.x; As[0][lk+1][lrow]=aR.y; As[0][lk+2][lrow]=aR.z; As[0][lk+3][lrow]=aR.w;
        Bs[0][lk+0][lrow]=bR.x; Bs[0][lk+1][lrow]=bR.y; Bs[0][lk+2][lrow]=bR.z; Bs[0][lk+3][lrow]=bR.w;
    }
    __syncthreads();
    int buf = 0;
    for (int k0 = GBK; k0 <= K; k0 += GBK) {
        bool more = (k0 < K);
        if (more) {
            int br = bn + lrow;
            aR = (arow_m >= 0) ? *reinterpret_cast<const float4*>(g_Hs + (size_t)arow_m*K + k0 + lk) : Z4;
            bR = (br < N)      ? *reinterpret_cast<const float4*>(B + (size_t)br*K + k0 + lk) : Z4;
        }
        #pragma unroll
        for (int kk = 0; kk < GBK; kk++) {
            float a[8], b[8];
            *reinterpret_cast<float4*>(a)   = *reinterpret_cast<const float4*>(&As[buf][kk][rm]);
            *reinterpret_cast<float4*>(a+4) = *reinterpret_cast<const float4*>(&As[buf][kk][rm+4]);
            *reinterpret_cast<float4*>(b)   = *reinterpret_cast<const float4*>(&Bs[buf][kk][rn]);
            *reinterpret_cast<float4*>(b+4) = *reinterpret_cast<const float4*>(&Bs[buf][kk][rn+4]);
            #pragma unroll
            for (int i = 0; i < 8; i++)
                #pragma unroll
                for (int j = 0; j < 8; j++)
                    acc[i][j] = fmaf(a[i], b[j], acc[i][j]);
        }
        if (more) {
            int nb = buf ^ 1;
            As[nb][lk+0][lrow]=aR.x; As[nb][lk+1][lrow]=aR.y; As[nb][lk+2][lrow]=aR.z; As[nb][lk+3][lrow]=aR.w;
            Bs[nb][lk+0][lrow]=bR.x; Bs[nb][lk+1][lrow]=bR.y; Bs[nb][lk+2][lrow]=bR.z; Bs[nb][lk+3][lrow]=bR.w;
        }
        __syncthreads();
        buf ^= 1;
    }
    #pragma unroll
    for (int i = 0; i < 8; i++) {
        int r = bm + rm + i;
        if (r >= count) continue;
        int m = g_rowmap[r];
        int t_ = m >> 6, b_ = m & 63;
        float* crow = out + (size_t)b_*(TMAX*VV) + (size_t)t_*VV;
        #pragma unroll
        for (int j = 0; j < 8; j++) {
            int n = bn + rn + j;
            if (n < N) crow[n] = acc[i][j] + bias[n];
        }
    }
}

// ---- fused attention: de/fbeta proj + scores + softmax + z + emb gather ----
__global__ __launch_bounds__(256)
void attention_fused(const float* __restrict__ features,
                     const float* __restrict__ W_full,
                     const float* __restrict__ W_emb,
                     const int*   __restrict__ captions,
                     const int*   __restrict__ lengths,
                     float* __restrict__ alphas_out, int t) {
    int b    = blockIdx.x;
    int tid  = threadIdx.x;
    int lane = tid & 31, wid = tid >> 5;
    int p = t & 1;
    __shared__ float h_s[HH];
    __shared__ float de_s[AA];
    __shared__ float fb_s[FF];
    __shared__ float wf_s[AA];
    __shared__ float sc[LL];
    __shared__ float red[8];

    for (int i = tid; i < HH; i += 256) h_s[i] = g_hc[p][b*1024 + i];
    for (int i = tid; i < AA; i += 256) wf_s[i] = W_full[i];
    __syncthreads();

    // de (cols tid, tid+256) + fbeta (cols tid+512, tid+768) via transposed W
    {
        float a0=0.f, a1=0.f, a2=0.f, a3=0.f;
        #pragma unroll 4
        for (int k = 0; k < HH; k++) {
            float hv = h_s[k];
            const float* w = g_WdfT + k*1024 + tid;
            a0 = fmaf(hv, w[0],   a0);
            a1 = fmaf(hv, w[256], a1);
            a2 = fmaf(hv, w[512], a2);
            a3 = fmaf(hv, w[768], a3);
        }
        de_s[tid]       = a0 + g_bdf[tid];
        de_s[tid + 256] = a1 + g_bdf[tid + 256];
        fb_s[tid]       = sigm(a2 + g_bdf[tid + 512]);
        fb_s[tid + 256] = sigm(a3 + g_bdf[tid + 768]);
    }
    __syncthreads();

    // scores: warp per l (strided)
    for (int l = wid; l < LL; l += 8) {
        const float* ea = g_enatt + ((size_t)b*LL + l)*AA;
        float s = 0.f;
        #pragma unroll 4
        for (int a = lane; a < AA; a += 32)
            s += tanhf(ea[a] + de_s[a]) * wf_s[a];
        #pragma unroll
        for (int o = 16; o; o >>= 1) s += __shfl_xor_sync(0xffffffffu, s, o);
        if (lane == 0) sc[l] = s;
    }
    __syncthreads();

    // block max
    float mx = -1e30f;
    for (int l = tid; l < LL; l += 256) mx = fmaxf(mx, sc[l]);
    #pragma unroll
    for (int o = 16; o; o >>= 1) mx = fmaxf(mx, __shfl_xor_sync(0xffffffffu, mx, o));
    if (lane == 0) red[wid] = mx;
    __syncthreads();
    if (wid == 0) {
        float v = (lane < 8) ? red[lane] : -1e30f;
        #pragma unroll
        for (int o = 4; o; o >>= 1) v = fmaxf(v, __shfl_xor_sync(0xffffffffu, v, o));
        if (lane == 0) red[0] = v;
    }
    __syncthreads();
    mx = red[0];
    __syncthreads();

    float sum = 0.f;
    for (int l = tid; l < LL; l += 256) {
        float e = expf(sc[l] - mx);
        sc[l] = e;
        sum += e;
    }
    #pragma unroll
    for (int o = 16; o; o >>= 1) sum += __shfl_xor_sync(0xffffffffu, sum, o);
    if (lane == 0) red[wid] = sum;
    __syncthreads();
    if (wid == 0) {
        float v = (lane < 8) ? red[lane] : 0.f;
        #pragma unroll
        for (int o = 4; o; o >>= 1) v += __shfl_xor_sync(0xffffffffu, v, o);
        if (lane == 0) red[0] = v;
    }
    __syncthreads();
    float inv = 1.f / red[0];

    bool active = (lengths[b] - 1) > t;

    for (int l = tid; l < LL; l += 256)
        alphas_out[(size_t)b*(TMAX*LL) + (size_t)t*LL + l] = active ? sc[l]*inv : 0.f;

    // z = (alpha @ feat_r[b]) * sigmoid(fbeta) -> x[:,512:]
    const float* fb_base = features + (size_t)b*FL;
    for (int f = tid; f < FF; f += 256) {
        float z = 0.f;
        #pragma unroll 4
        for (int l = 0; l < LL; l++)
            z = fmaf(sc[l], fb_base[(size_t)l*FF + f], z);
        g_x[b*1024 + 512 + f] = z * inv * fb_s[f];
    }

    // embedding -> x[:,0:512]
    int cap = captions[b*TT + t];
    for (int e = tid; e < EE; e += 256)
        g_x[b*1024 + e] = W_emb[(size_t)cap*EE + e];
}

// ---- fused gates + cell: block owns j-strip of 4 (all 4 gates), all b ------
__global__ __launch_bounds__(256)
void gates_cell(const float* __restrict__ W_ih, const float* __restrict__ W_hh,
                const float* __restrict__ b_ih, const float* __restrict__ b_hh,
                const int* __restrict__ lengths, int t) {
    __shared__ float As[16][66];
    __shared__ float Bs[16][16];
    __shared__ float gs[16][65];
    int blk = blockIdx.x;          // 0..127 -> j in [blk*4, blk*4+4)
    int tid = threadIdx.x;
    int tx = tid & 15, ty = tid >> 4;
    int p = t & 1;
    float acc[4] = {0,0,0,0};
    int gcol_c = (tx >> 2)*512 + blk*4 + (tx & 3);          // column for compute thread
    int arow = tid >> 2;                                     // loader: row 0..63
    int k4   = (tid & 3) * 4;
    int cB   = tid >> 2;                                     // loader col for Bs (tid<64)
    int gcol_l = (cB >> 2)*512 + blk*4 + (cB & 3);

    #pragma unroll
    for (int phase = 0; phase < 2; phase++) {
        const float* Ab = phase ? g_hc[p] : g_x;             // both row stride 1024
        const float* Wb = phase ? W_hh : W_ih;
        int wstride = phase ? 512 : 1024;
        int Kp      = phase ? 512 : 1024;
        for (int k0 = 0; k0 < Kp; k0 += 16) {
            float4 av = *reinterpret_cast<const float4*>(Ab + (size_t)arow*1024 + k0 + k4);
            As[k4+0][arow]=av.x; As[k4+1][arow]=av.y; As[k4+2][arow]=av.z; As[k4+3][arow]=av.w;
            if (tid < 64) {
                float4 wv = *reinterpret_cast<const float4*>(Wb + (size_t)gcol_l*wstride + k0 + k4);
                Bs[k4+0][cB]=wv.x; Bs[k4+1][cB]=wv.y; Bs[k4+2][cB]=wv.z; Bs[k4+3][cB]=wv.w;
            }
            __syncthreads();
            #pragma unroll
            for (int kk = 0; kk < 16; kk++) {
                float bval = Bs[kk][tx];
                #pragma unroll
                for (int i = 0; i < 4; i++)
                    acc[i] = fmaf(As[kk][ty*4 + i], bval, acc[i]);
            }
            __syncthreads();
        }
    }
    float bsum = b_ih[gcol_c] + b_hh[gcol_c];
    #pragma unroll
    for (int i = 0; i < 4; i++) gs[tx][ty*4 + i] = acc[i] + bsum;
    __syncthreads();

    // cell update: 256 threads = 64 b x 4 local j
    int b  = tid & 63;
    int jl = tid >> 6;
    int j  = blk*4 + jl;
    float gi = gs[ 0 + jl][b];
    float gf = gs[ 4 + jl][b];
    float gg = gs[ 8 + jl][b];
    float go = gs[12 + jl][b];
    float h_old = g_hc[p][b*1024 + j];
    float c_old = g_hc[p][b*1024 + 512 + j];
    float cn = sigm(gf)*c_old + sigm(gi)*tanhf(gg);
    float hn = sigm(go)*tanhf(cn);
    g_Hs[(size_t)t*(BB*HH) + b*HH + j] = hn;
    bool act = (lengths[b] - 1) > t;
    g_hc[p^1][b*1024 + j]       = act ? hn : h_old;
    g_hc[p^1][b*1024 + 512 + j] = act ? cn : c_old;
}

// -------------------- host launcher -----------------------------------------
extern "C" void kernel_launch(void* const* d_in, const int* in_sizes, int n_in,
                              void* d_out, int out_size) {
    const float* features = (const float*)d_in[0];
    const int*   captions = (const int*)  d_in[1];
    const int*   lengths  = (const int*)  d_in[2];
    const float* W_emb    = (const float*)d_in[3];
    const float* W_enc    = (const float*)d_in[4];
    const float* b_enc    = (const float*)d_in[5];
    const float* W_dec    = (const float*)d_in[6];
    const float* b_dec    = (const float*)d_in[7];
    const float* W_full   = (const float*)d_in[8];
    /* b_full (d_in[9]) softmax-invariant: unused */
    const float* W_fbeta  = (const float*)d_in[10];
    const float* b_fbeta  = (const float*)d_in[11];
    const float* W_ih     = (const float*)d_in[12];
    const float* W_hh     = (const float*)d_in[13];
    const float* b_ih     = (const float*)d_in[14];
    const float* b_hh     = (const float*)d_in[15];
    const float* W_out    = (const float*)d_in[16];
    const float* b_out    = (const float*)d_in[17];
    const float* W_init_h = (const float*)d_in[18];
    const float* b_init_h = (const float*)d_in[19];
    const float* W_init_c = (const float*)d_in[20];
    const float* b_init_c = (const float*)d_in[21];

    float* out = (float*)d_out;
    float* alphas_out = out + (size_t)BB*TMAX*VV;

    (void)n_in; (void)in_sizes; (void)out_size;

    // device addresses of __device__ globals (host symbol != device address)
    float *p_enatt, *p_meanf, *p_hc0, *p_Winit, *p_binit;
    cudaGetSymbolAddress((void**)&p_enatt, g_enatt);
    cudaGetSymbolAddress((void**)&p_meanf, g_meanf);
    cudaGetSymbolAddress((void**)&p_hc0,   g_hc);        // buffer 0
    cudaGetSymbolAddress((void**)&p_Winit, g_Winit);
    cudaGetSymbolAddress((void**)&p_binit, g_binit);

    // one-time setup
    setup_all<<<2048, 256>>>(W_dec, b_dec, W_fbeta, b_fbeta,
                             W_init_h, b_init_h, W_init_c, b_init_c);
    setup_rowmap<<<1, 256>>>(lengths);
    zero_inactive<<<TMAX*BB, 256>>>(lengths, out);

    // en_att = feat_r @ W_enc^T + b_enc   (M=12544, N=512, K=512)
    {
        dim3 g(AA/GBN, ENATT_M/GBM);   // (4, 98)
        gemm128<<<g, 256>>>(features, W_enc, b_enc, p_enatt, ENATT_M, AA, FF);
    }

    // mean over L, then combined [h0|c0] init GEMM (N=1024)
    mean_kernel<<<(BB*FF*32 + 255)/256, 256>>>(features);
    {
        dim3 g(1024/BN, 1);
        gemm_nt_bias<<<g, 256>>>(p_meanf, p_Winit, p_binit, p_hc0, BB, 1024, FF);
    }

    // recurrence: 2 kernels/step
    for (int t = 0; t < TMAX; t++) {
        attention_fused<<<BB, 256>>>(features, W_full, W_emb, captions, lengths,
                                     alphas_out, t);
        gates_cell<<<128, 256>>>(W_ih, W_hh, b_ih, b_hh, lengths, t);
    }

    // compacted output projection (active rows only)
    {
        dim3 g((VV + GBN - 1)/GBN, (TMAX*BB + GBM - 1)/GBM);  // (79, 16)
        gemm_preds_c<<<g, 256>>>(W_out, b_out, out);
    }
}

// round 8
// speedup vs baseline: 1.3046x; 1.1778x over previous
#include <cuda_runtime.h>
#include <cuda_bf16.h>
#include <math.h>

// Problem constants
#define BB   64
#define TT   32
#define TMAX 31
#define FF   512
#define LL   196
#define EE   512
#define HH   512
#define AA   512
#define VV   10000

#define FL   (FF*LL)        // 100352
#define ENATT_M (BB*LL)     // 12544
#define NB   128            // persistent grid size (<= SM count -> co-resident)

// -------------------- scratch (static device globals; no allocs) ------------
__device__ float g_enatt[BB*LL*AA];        // 25.7 MB
__device__ float g_meanf[BB*FF];
__device__ float g_hc[2][1024*BB];         // TRANSPOSED: [j*64+b]; j<512 = h_j, j>=512 = c_{j-512}
__device__ float g_xT[1024*BB];            // TRANSPOSED x: [j*64+b]; j<512 emb, j>=512 z
__device__ float g_defb[BB*1024];          // [b][j]; j<512 de, j>=512 sigm(fbeta)
__device__ float g_Hs[TMAX*BB*HH];         // row-major rows m=t*64+b (A of preds GEMM)
__device__ float g_Winit[1024*512];        // concat [W_init_h; W_init_c]
__device__ float g_binit[1024];
__device__ int   g_rowmap[TMAX*BB];
__device__ int   g_count;
__device__ unsigned g_bar;                 // software grid-barrier counter

// -------------------- fast math helpers -------------------------------------
__device__ __forceinline__ float fsigm(float x) {
    float e = __expf(fminf(-x, 30.f));
    return __fdividef(1.f, 1.f + e);
}
__device__ __forceinline__ float ftanh_e(float x) {     // accurate-ish (cell state)
    x = fminf(fmaxf(x, -15.f), 15.f);
    float e = __expf(2.f*x);
    return __fdividef(e - 1.f, e + 1.f);
}
__device__ __forceinline__ float ftanh_a(float x) {     // 1-MUFU approx (scores only)
    float r; asm("tanh.approx.f32 %0, %1;" : "=f"(r) : "f"(x)); return r;
}

// -------------------- software grid barrier ---------------------------------
__device__ __forceinline__ void grid_bar(unsigned target) {
    __syncthreads();
    if (threadIdx.x == 0) {
        __threadfence();                       // release: drain my stcg writes
        atomicAdd(&g_bar, 1u);
        while (atomicAdd(&g_bar, 0u) < target) __nanosleep(64);
        __threadfence();                       // acquire: order subsequent ldcg reads
    }
    __syncthreads();
}

// -------------------- setup ---------------------------------------------------
__global__ void setup_all(const float* __restrict__ Wih_i, const float* __restrict__ bih_i,
                          const float* __restrict__ Wic_i, const float* __restrict__ bic_i) {
    int i = blockIdx.x*blockDim.x + threadIdx.x;      // 0 .. 524287
    int j = i >> 9, k = i & 511;
    g_Winit[(size_t)j*512 + k] = (j < 512) ? Wih_i[j*512 + k] : Wic_i[(j-512)*512 + k];
    if (i < 1024) g_binit[i] = (i < 512) ? bih_i[i] : bic_i[i-512];
    if (i == 0) g_bar = 0u;
}

__global__ void setup_rowmap(const int* __restrict__ lengths) {
    __shared__ int nt[TMAX+1];
    int tid = threadIdx.x;
    if (tid < TMAX) {
        int n = 0;
        for (int b = 0; b < BB; b++) n += (lengths[b]-1 > tid);
        nt[tid] = n;
    }
    __syncthreads();
    if (tid == 0) {
        int pre = 0;
        for (int t = 0; t < TMAX; t++) { int n = nt[t]; nt[t] = pre; pre += n; }
        nt[TMAX] = pre;
        g_count = pre;
    }
    __syncthreads();
    for (int t = 0; t < TMAX; t++) {
        int base = nt[t];
        int cnt  = nt[t+1] - base;
        for (int b = tid; b < cnt; b += blockDim.x)
            g_rowmap[base + b] = t*64 + b;   // lengths sorted desc -> active b's are a prefix
    }
}

__global__ void zero_inactive(const int* __restrict__ lengths, float* __restrict__ out) {
    int m = blockIdx.x;           // 0..1983
    int t = m >> 6, b = m & 63;
    if (lengths[b]-1 > t) return;
    float4* p = reinterpret_cast<float4*>(out + (size_t)b*(TMAX*VV) + (size_t)t*VV);
    float4 z = make_float4(0,0,0,0);
    for (int i = threadIdx.x; i < VV/4; i += blockDim.x) p[i] = z;
}

// -------------------- mean over L (raw [B,F,L] layout) ----------------------
__global__ void mean_kernel(const float* __restrict__ features) {
    int gw   = (blockIdx.x*blockDim.x + threadIdx.x) >> 5;
    int lane = threadIdx.x & 31;
    if (gw >= BB*FF) return;
    int b = gw >> 9, f = gw & 511;
    const float* p = features + (size_t)b*FL + (size_t)f*LL;
    float s = 0.f;
    for (int l = lane; l < LL; l += 32) s += p[l];
    #pragma unroll
    for (int o = 16; o; o >>= 1) s += __shfl_xor_sync(0xffffffffu, s, o);
    if (lane == 0) g_meanf[gw] = s * (1.f/196.f);
}

// ---- init GEMM: g_hc[0][j][b] = meanf[b] @ Winit[j] + binit[j] (transposed C)
#define BM 64
#define BN 64
#define BK 16
__global__ __launch_bounds__(256)
void gemm_init() {
    __shared__ float As[BM][BK+1];
    __shared__ float Bs[BN][BK+1];
    const int K = 512;
    int bn = blockIdx.x * BN;             // over N=1024
    int tid = threadIdx.x;
    int lr = tid >> 2, lk = (tid & 3) * 4;
    int rm = (tid & 15) * 4, rn = (tid >> 4) * 4;
    float acc[4][4] = {};
    for (int k0 = 0; k0 < K; k0 += BK) {
        float4 av = *reinterpret_cast<const float4*>(g_meanf + (size_t)lr*K + k0 + lk);
        float4 bv = *reinterpret_cast<const float4*>(g_Winit + (size_t)(bn+lr)*K + k0 + lk);
        As[lr][lk+0]=av.x; As[lr][lk+1]=av.y; As[lr][lk+2]=av.z; As[lr][lk+3]=av.w;
        Bs[lr][lk+0]=bv.x; Bs[lr][lk+1]=bv.y; Bs[lr][lk+2]=bv.z; Bs[lr][lk+3]=bv.w;
        __syncthreads();
        #pragma unroll
        for (int kk = 0; kk < BK; kk++) {
            float a[4], bb[4];
            #pragma unroll
            for (int i = 0; i < 4; i++) a[i]  = As[rm+i][kk];
            #pragma unroll
            for (int j = 0; j < 4; j++) bb[j] = Bs[rn+j][kk];
            #pragma unroll
            for (int i = 0; i < 4; i++)
                #pragma unroll
                for (int j = 0; j < 4; j++)
                    acc[i][j] = fmaf(a[i], bb[j], acc[i][j]);
        }
        __syncthreads();
    }
    #pragma unroll
    for (int i = 0; i < 4; i++) {
        int m = rm + i;                    // b
        #pragma unroll
        for (int j = 0; j < 4; j++) {
            int n = bn + rn + j;           // j-index
            g_hc[0][(size_t)n*64 + m] = acc[i][j] + g_binit[n];
        }
    }
}

// -------------------- big double-buffered SGEMM 128x128x8 -------------------
#define GBM 128
#define GBN 128
#define GBK 8
__global__ __launch_bounds__(256, 2)
void gemm128(const float* __restrict__ A, const float* __restrict__ B,
             const float* __restrict__ bias, float* __restrict__ C,
             int M, int N, int K) {
    __shared__ float As[2][GBK][GBM];
    __shared__ float Bs[2][GBK][GBN];
    int bm = blockIdx.y * GBM, bn = blockIdx.x * GBN;
    int tid = threadIdx.x;
    int lrow = tid >> 1;
    int lk   = (tid & 1) * 4;
    int tx = tid & 15, ty = tid >> 4;
    int rm = ty*8, rn = tx*8;
    float acc[8][8] = {};
    float4 aR, bR;
    const float4 Z4 = make_float4(0,0,0,0);
    {
        int ar = bm + lrow, br = bn + lrow;
        aR = (ar < M) ? *reinterpret_cast<const float4*>(A + (size_t)ar*K + lk) : Z4;
        bR = (br < N) ? *reinterpret_cast<const float4*>(B + (size_t)br*K + lk) : Z4;
        As[0][lk+0][lrow]=aR.x; As[0][lk+1][lrow]=aR.y; As[0][lk+2][lrow]=aR.z; As[0][lk+3][lrow]=aR.w;
        Bs[0][lk+0][lrow]=bR.x; Bs[0][lk+1][lrow]=bR.y; Bs[0][lk+2][lrow]=bR.z; Bs[0][lk+3][lrow]=bR.w;
    }
    __syncthreads();
    int buf = 0;
    for (int k0 = GBK; k0 <= K; k0 += GBK) {
        bool more = (k0 < K);
        if (more) {
            int ar = bm + lrow, br = bn + lrow;
            aR = (ar < M) ? *reinterpret_cast<const float4*>(A + (size_t)ar*K + k0 + lk) : Z4;
            bR = (br < N) ? *reinterpret_cast<const float4*>(B + (size_t)br*K + k0 + lk) : Z4;
        }
        #pragma unroll
        for (int kk = 0; kk < GBK; kk++) {
            float a[8], b[8];
            *reinterpret_cast<float4*>(a)   = *reinterpret_cast<const float4*>(&As[buf][kk][rm]);
            *reinterpret_cast<float4*>(a+4) = *reinterpret_cast<const float4*>(&As[buf][kk][rm+4]);
            *reinterpret_cast<float4*>(b)   = *reinterpret_cast<const float4*>(&Bs[buf][kk][rn]);
            *reinterpret_cast<float4*>(b+4) = *reinterpret_cast<const float4*>(&Bs[buf][kk][rn+4]);
            #pragma unroll
            for (int i = 0; i < 8; i++)
                #pragma unroll
                for (int j = 0; j < 8; j++)
                    acc[i][j] = fmaf(a[i], b[j], acc[i][j]);
        }
        if (more) {
            int nb = buf ^ 1;
            As[nb][lk+0][lrow]=aR.x; As[nb][lk+1][lrow]=aR.y; As[nb][lk+2][lrow]=aR.z; As[nb][lk+3][lrow]=aR.w;
            Bs[nb][lk+0][lrow]=bR.x; Bs[nb][lk+1][lrow]=bR.y; Bs[nb][lk+2][lrow]=bR.z; Bs[nb][lk+3][lrow]=bR.w;
        }
        __syncthreads();
        buf ^= 1;
    }
    #pragma unroll
    for (int i = 0; i < 8; i++) {
        int m = bm + rm + i;
        if (m >= M) continue;
        float* crow = C + (size_t)m*N;
        #pragma unroll
        for (int j = 0; j < 8; j++) {
            int n = bn + rn + j;
            if (n < N) crow[n] = acc[i][j] + (bias ? bias[n] : 0.f);
        }
    }
}

// ------ preds GEMM on compacted active rows (A rows via g_rowmap -> g_Hs) ---
__global__ __launch_bounds__(256, 2)
void gemm_preds_c(const float* __restrict__ B, const float* __restrict__ bias,
                  float* __restrict__ out) {
    __shared__ float As[2][GBK][GBM];
    __shared__ float Bs[2][GBK][GBN];
    const int N = VV, K = HH;
    int count = g_count;
    int bm = blockIdx.y * GBM, bn = blockIdx.x * GBN;
    if (bm >= count) return;
    int tid = threadIdx.x;
    int lrow = tid >> 1;
    int lk   = (tid & 1) * 4;
    int tx = tid & 15, ty = tid >> 4;
    int rm = ty*8, rn = tx*8;
    float acc[8][8] = {};
    float4 aR, bR;
    const float4 Z4 = make_float4(0,0,0,0);
    int arow_m = (bm + lrow < count) ? g_rowmap[bm + lrow] : -1;
    {
        int br = bn + lrow;
        aR = (arow_m >= 0) ? *reinterpret_cast<const float4*>(g_Hs + (size_t)arow_m*K + lk) : Z4;
        bR = (br < N)      ? *reinterpret_cast<const float4*>(B + (size_t)br*K + lk) : Z4;
        As[0][lk+0][lrow]=aR.x; As[0][lk+1][lrow]=aR.y; As[0][lk+2][lrow]=aR.z; As[0][lk+3][lrow]=aR.w;
        Bs[0][lk+0][lrow]=bR.x; Bs[0][lk+1][lrow]=bR.y; Bs[0][lk+2][lrow]=bR.z; Bs[0][lk+3][lrow]=bR.w;
    }
    __syncthreads();
    int buf = 0;
    for (int k0 = GBK; k0 <= K; k0 += GBK) {
        bool more = (k0 < K);
        if (more) {
            int br = bn + lrow;
            aR = (arow_m >= 0) ? *reinterpret_cast<const float4*>(g_Hs + (size_t)arow_m*K + k0 + lk) : Z4;
            bR = (br < N)      ? *reinterpret_cast<const float4*>(B + (size_t)br*K + k0 + lk) : Z4;
        }
        #pragma unroll
        for (int kk = 0; kk < GBK; kk++) {
            float a[8], b[8];
            *reinterpret_cast<float4*>(a)   = *reinterpret_cast<const float4*>(&As[buf][kk][rm]);
            *reinterpret_cast<float4*>(a+4) = *reinterpret_cast<const float4*>(&As[buf][kk][rm+4]);
            *reinterpret_cast<float4*>(b)   = *reinterpret_cast<const float4*>(&Bs[buf][kk][rn]);
            *reinterpret_cast<float4*>(b+4) = *reinterpret_cast<const float4*>(&Bs[buf][kk][rn+4]);
            #pragma unroll
            for (int i = 0; i < 8; i++)
                #pragma unroll
                for (int j = 0; j < 8; j++)
                    acc[i][j] = fmaf(a[i], b[j], acc[i][j]);
        }
        if (more) {
            int nb = buf ^ 1;
            As[nb][lk+0][lrow]=aR.x; As[nb][lk+1][lrow]=aR.y; As[nb][lk+2][lrow]=aR.z; As[nb][lk+3][lrow]=aR.w;
            Bs[nb][lk+0][lrow]=bR.x; Bs[nb][lk+1][lrow]=bR.y; Bs[nb][lk+2][lrow]=bR.z; Bs[nb][lk+3][lrow]=bR.w;
        }
        __syncthreads();
        buf ^= 1;
    }
    #pragma unroll
    for (int i = 0; i < 8; i++) {
        int r = bm + rm + i;
        if (r >= count) continue;
        int m = g_rowmap[r];
        int t_ = m >> 6, b_ = m & 63;
        float* crow = out + (size_t)b_*(TMAX*VV) + (size_t)t_*VV;
        #pragma unroll
        for (int j = 0; j < 8; j++) {
            int n = bn + rn + j;
            if (n < N) crow[n] = acc[i][j] + bias[n];
        }
    }
}

// ============ persistent recurrence kernel (whole 31-step loop) ==============
__global__ __launch_bounds__(256)
void recurrence(const float* __restrict__ features,
                const float* __restrict__ W_dec, const float* __restrict__ b_dec,
                const float* __restrict__ W_fb,  const float* __restrict__ b_fb,
                const float* __restrict__ W_full,
                const float* __restrict__ W_emb,
                const int*   __restrict__ captions,
                const int*   __restrict__ lengths,
                const float* __restrict__ W_ih, const float* __restrict__ W_hh,
                const float* __restrict__ b_ih, const float* __restrict__ b_hh,
                float* __restrict__ alphas_out)
{
    const int blk = blockIdx.x, tid = threadIdx.x;
    __shared__ float hs[64][64];           // P1 h chunk [kk][b]
    __shared__ float de_s[512], wf_s[512], sc[200], red[8];
    __shared__ float As[16][68];           // P3 A tile [kk][b]
    __shared__ float Bs2[16][16];          // P3 W tile [k][col]
    __shared__ float gs[16][65];           // P3 gates  [col][b]
    unsigned ep = 0;

    for (int t = 0; t < TMAX; t++) {
        const int p = t & 1;

        // ---------------- P1: de/fbeta projection (blocks 0..127) ------------
        if (blk < 128) {
            const bool isdec = (blk < 64);
            const int j = (blk & 63) * 8 + (tid >> 5);     // warp -> one j row
            const int lane = tid & 31;
            const float* wrow = (isdec ? W_dec : W_fb) + (size_t)j * 512;
            const float* hb   = g_hc[p];
            float acc0 = 0.f, acc1 = 0.f;
            for (int k0 = 0; k0 < 512; k0 += 64) {
                #pragma unroll
                for (int r = 0; r < 4; r++) {
                    int idx = tid + r*256;
                    int kk = idx >> 4, b4 = (idx & 15) * 4;
                    float4 v = __ldcg(reinterpret_cast<const float4*>(hb + (size_t)(k0+kk)*64 + b4));
                    *reinterpret_cast<float4*>(&hs[kk][b4]) = v;
                }
                __syncthreads();
                #pragma unroll 8
                for (int kk = 0; kk < 64; kk++) {
                    float w = __ldg(wrow + k0 + kk);
                    acc0 = fmaf(w, hs[kk][lane],      acc0);
                    acc1 = fmaf(w, hs[kk][lane + 32], acc1);
                }
                __syncthreads();
            }
            float bj = isdec ? b_dec[j] : b_fb[j];
            if (isdec) {
                __stcg(&g_defb[lane*1024 + j],        acc0 + bj);
                __stcg(&g_defb[(lane+32)*1024 + j],   acc1 + bj);
            } else {
                __stcg(&g_defb[lane*1024 + 512 + j],      fsigm(acc0 + bj));
                __stcg(&g_defb[(lane+32)*1024 + 512 + j], fsigm(acc1 + bj));
            }
        }
        ep++; grid_bar(ep * NB);

        // ---------------- P2: attention + softmax + z + emb (blocks 0..63) ---
        if (blk < 64) {
            const int b = blk;
            const int lane = tid & 31, wid = tid >> 5;
            for (int i = tid; i < 512; i += 256) {
                de_s[i] = __ldcg(&g_defb[b*1024 + i]);
                wf_s[i] = W_full[i];
            }
            __syncthreads();

            for (int l = wid; l < LL; l += 8) {
                const float* ea = g_enatt + ((size_t)b*LL + l)*AA;
                float s = 0.f;
                #pragma unroll 4
                for (int a = lane; a < AA; a += 32)
                    s += ftanh_a(__ldg(ea + a) + de_s[a]) * wf_s[a];
                #pragma unroll
                for (int o = 16; o; o >>= 1) s += __shfl_xor_sync(0xffffffffu, s, o);
                if (lane == 0) sc[l] = s;
            }
            __syncthreads();

            float mx = -1e30f;
            for (int l = tid; l < LL; l += 256) mx = fmaxf(mx, sc[l]);
            #pragma unroll
            for (int o = 16; o; o >>= 1) mx = fmaxf(mx, __shfl_xor_sync(0xffffffffu, mx, o));
            if (lane == 0) red[wid] = mx;
            __syncthreads();
            if (wid == 0) {
                float v = (lane < 8) ? red[lane] : -1e30f;
                #pragma unroll
                for (int o = 4; o; o >>= 1) v = fmaxf(v, __shfl_xor_sync(0xffffffffu, v, o));
                if (lane == 0) red[0] = v;
            }
            __syncthreads();
            mx = red[0];
            __syncthreads();

            float sum = 0.f;
            for (int l = tid; l < LL; l += 256) {
                float e = __expf(sc[l] - mx);
                sc[l] = e;
                sum += e;
            }
            #pragma unroll
            for (int o = 16; o; o >>= 1) sum += __shfl_xor_sync(0xffffffffu, sum, o);
            if (lane == 0) red[wid] = sum;
            __syncthreads();
            if (wid == 0) {
                float v = (lane < 8) ? red[lane] : 0.f;
                #pragma unroll
                for (int o = 4; o; o >>= 1) v += __shfl_xor_sync(0xffffffffu, v, o);
                if (lane == 0) red[0] = v;
            }
            __syncthreads();
            float inv = __fdividef(1.f, red[0]);

            bool active = (lengths[b] - 1) > t;
            for (int l = tid; l < LL; l += 256)
                alphas_out[(size_t)b*(TMAX*LL) + (size_t)t*LL + l] = active ? sc[l]*inv : 0.f;

            // z = (alpha @ feat_r[b]) * sigm(fbeta) -> xT[512+f][b]
            const float* fbb = features + (size_t)b*FL;
            for (int f = tid; f < FF; f += 256) {
                float z = 0.f;
                #pragma unroll 4
                for (int l = 0; l < LL; l++)
                    z = fmaf(sc[l], __ldg(fbb + (size_t)l*FF + f), z);
                float gate = __ldcg(&g_defb[b*1024 + 512 + f]);
                __stcg(&g_xT[(size_t)(512+f)*64 + b], z * inv * gate);
            }
            // embedding -> xT[e][b]
            int cap = captions[b*TT + t];
            for (int e = tid; e < EE; e += 256)
                __stcg(&g_xT[(size_t)e*64 + b], __ldg(&W_emb[(size_t)cap*EE + e]));
        }
        ep++; grid_bar(ep * NB);

        // ---------------- P3: gates GEMM + LSTM cell (blocks 0..127) ---------
        if (blk < 128) {
            const int txx = tid & 15, tyy = tid >> 4;
            float acc[4] = {0,0,0,0};
            const int gcol_c = (txx >> 2)*512 + blk*4 + (txx & 3);
            const int kk_a = tid >> 4, b4 = (tid & 15) * 4;
            const int cB = tid >> 2, k4 = (tid & 3) * 4;
            const int gcol_l = (cB >> 2)*512 + blk*4 + (cB & 3);

            #pragma unroll
            for (int phase = 0; phase < 2; phase++) {
                const float* Ab = phase ? g_hc[p] : g_xT;    // [j*64+b]
                const float* Wb = phase ? W_hh : W_ih;
                const int wstride = phase ? 512 : 1024;
                const int Kp      = phase ? 512 : 1024;
                for (int k0 = 0; k0 < Kp; k0 += 16) {
                    float4 av = __ldcg(reinterpret_cast<const float4*>(Ab + (size_t)(k0 + kk_a)*64 + b4));
                    *reinterpret_cast<float4*>(&As[kk_a][b4]) = av;
                    if (tid < 64) {
                        float4 wv = *reinterpret_cast<const float4*>(Wb + (size_t)gcol_l*wstride + k0 + k4);
                        Bs2[k4+0][cB]=wv.x; Bs2[k4+1][cB]=wv.y; Bs2[k4+2][cB]=wv.z; Bs2[k4+3][cB]=wv.w;
                    }
                    __syncthreads();
                    #pragma unroll
                    for (int kk = 0; kk < 16; kk++) {
                        float bval = Bs2[kk][txx];
                        #pragma unroll
                        for (int i = 0; i < 4; i++)
                            acc[i] = fmaf(As[kk][tyy*4 + i], bval, acc[i]);
                    }
                    __syncthreads();
                }
            }
            float bsum = b_ih[gcol_c] + b_hh[gcol_c];
            #pragma unroll
            for (int i = 0; i < 4; i++) gs[txx][tyy*4 + i] = acc[i] + bsum;
            __syncthreads();

            // cell update: 256 threads = 64 b x 4 local j
            int b  = tid & 63;
            int jl = tid >> 6;
            int j  = blk*4 + jl;
            float gi = gs[ 0 + jl][b];
            float gf = gs[ 4 + jl][b];
            float gg = gs[ 8 + jl][b];
            float go = gs[12 + jl][b];
            float h_old = __ldcg(&g_hc[p][(size_t)j*64 + b]);
            float c_old = __ldcg(&g_hc[p][(size_t)(512+j)*64 + b]);
            float cn = fsigm(gf)*c_old + fsigm(gi)*ftanh_e(gg);
            float hn = fsigm(go)*ftanh_e(cn);
            g_Hs[(size_t)t*(BB*HH) + b*HH + j] = hn;
            bool act = (lengths[b] - 1) > t;
            __stcg(&g_hc[p^1][(size_t)j*64 + b],       act ? hn : h_old);
            __stcg(&g_hc[p^1][(size_t)(512+j)*64 + b], act ? cn : c_old);
            __syncthreads();
        }
        ep++; grid_bar(ep * NB);
    }
}

// -------------------- host launcher -----------------------------------------
extern "C" void kernel_launch(void* const* d_in, const int* in_sizes, int n_in,
                              void* d_out, int out_size) {
    const float* features = (const float*)d_in[0];
    const int*   captions = (const int*)  d_in[1];
    const int*   lengths  = (const int*)  d_in[2];
    const float* W_emb    = (const float*)d_in[3];
    const float* W_enc    = (const float*)d_in[4];
    const float* b_enc    = (const float*)d_in[5];
    const float* W_dec    = (const float*)d_in[6];
    const float* b_dec    = (const float*)d_in[7];
    const float* W_full   = (const float*)d_in[8];
    /* b_full (d_in[9]) softmax-invariant: unused */
    const float* W_fbeta  = (const float*)d_in[10];
    const float* b_fbeta  = (const float*)d_in[11];
    const float* W_ih     = (const float*)d_in[12];
    const float* W_hh     = (const float*)d_in[13];
    const float* b_ih     = (const float*)d_in[14];
    const float* b_hh     = (const float*)d_in[15];
    const float* W_out    = (const float*)d_in[16];
    const float* b_out    = (const float*)d_in[17];
    const float* W_init_h = (const float*)d_in[18];
    const float* b_init_h = (const float*)d_in[19];
    const float* W_init_c = (const float*)d_in[20];
    const float* b_init_c = (const float*)d_in[21];

    float* out = (float*)d_out;
    float* alphas_out = out + (size_t)BB*TMAX*VV;

    (void)n_in; (void)in_sizes; (void)out_size;

    // device address of g_enatt for the generic GEMM (host symbol != device addr!)
    float* p_enatt;
    cudaGetSymbolAddress((void**)&p_enatt, g_enatt);

    // one-time setup (also resets the grid-barrier counter every launch/replay)
    setup_all<<<2048, 256>>>(W_init_h, b_init_h, W_init_c, b_init_c);
    setup_rowmap<<<1, 256>>>(lengths);
    zero_inactive<<<TMAX*BB, 256>>>(lengths, out);

    // en_att = feat_r @ W_enc^T + b_enc   (M=12544, N=512, K=512)
    {
        dim3 g(AA/GBN, ENATT_M/GBM);   // (4, 98)
        gemm128<<<g, 256>>>(features, W_enc, b_enc, p_enatt, ENATT_M, AA, FF);
    }

    // mean over L, then combined transposed [h0|c0] init GEMM
    mean_kernel<<<(BB*FF*32 + 255)/256, 256>>>(features);
    gemm_init<<<16, 256>>>();

    // whole recurrence in ONE persistent kernel (grid <= SM count)
    recurrence<<<NB, 256>>>(features, W_dec, b_dec, W_fbeta, b_fbeta, W_full,
                            W_emb, captions, lengths, W_ih, W_hh, b_ih, b_hh,
                            alphas_out);

    // compacted output projection (active rows only)
    {
        dim3 g((VV + GBN - 1)/GBN, (TMAX*BB + GBM - 1)/GBM);  // (79, 16)
        gemm_preds_c<<<g, 256>>>(W_out, b_out, out);
    }
}

// round 10
// speedup vs baseline: 1.3682x; 1.0488x over previous
#include <cuda_runtime.h>
#include <cuda_bf16.h>
#include <math.h>

// Problem constants
#define BB   64
#define TT   32
#define TMAX 31
#define FF   512
#define LL   196
#define EE   512
#define HH   512
#define AA   512
#define VV   10000

#define FL   (FF*LL)        // 100352
#define ENATT_M (BB*LL)     // 12544
#define NB   128            // persistent grid size (<= SM count -> co-resident)

// -------------------- scratch (static device globals; no allocs) ------------
__device__ float g_enatt[BB*LL*AA];        // 25.7 MB
__device__ float g_meanf[BB*FF];
__device__ float g_hc[2][1024*BB];         // TRANSPOSED: [j*64+b]; j<512 = h_j, j>=512 = c_{j-512}
__device__ float g_xT[1024*BB];            // TRANSPOSED x: [j*64+b]; j<512 emb, j>=512 z
__device__ float g_defb[BB*1024];          // [b][j]; j<512 de, j>=512 sigm(fbeta)
__device__ float g_Hs[TMAX*BB*HH];         // row-major rows m=t*64+b (A of preds GEMM)
__device__ float g_Winit[1024*512];        // concat [W_init_h; W_init_c]
__device__ float g_binit[1024];
__device__ int   g_rowmap[TMAX*BB];
__device__ int   g_count;
__device__ unsigned g_bar;                 // software grid-barrier counter

// -------------------- fast math helpers -------------------------------------
__device__ __forceinline__ float fsigm(float x) {
    float e = __expf(fminf(-x, 30.f));
    return __fdividef(1.f, 1.f + e);
}
__device__ __forceinline__ float ftanh_e(float x) {     // accurate-ish (cell state)
    x = fminf(fmaxf(x, -15.f), 15.f);
    float e = __expf(2.f*x);
    return __fdividef(e - 1.f, e + 1.f);
}
__device__ __forceinline__ float ftanh_a(float x) {     // 1-MUFU approx (scores only)
    float r; asm("tanh.approx.f32 %0, %1;" : "=f"(r) : "f"(x)); return r;
}

// ------- software grid barrier: atomic arrive, LD.CG poll (no RMW storm) -----
__device__ __forceinline__ void grid_bar(unsigned target) {
    __syncthreads();
    if (threadIdx.x == 0) {
        __threadfence();                       // release: drain my stcg writes
        atomicAdd(&g_bar, 1u);
        unsigned v;
        for (;;) {
            asm volatile("ld.global.cg.u32 %0, [%1];" : "=r"(v) : "l"(&g_bar) : "memory");
            if (v >= target) break;
            __nanosleep(32);
        }
        __threadfence();                       // acquire: order subsequent ldcg reads
    }
    __syncthreads();
}

// -------------------- setup ---------------------------------------------------
__global__ void setup_all(const float* __restrict__ Wih_i, const float* __restrict__ bih_i,
                          const float* __restrict__ Wic_i, const float* __restrict__ bic_i) {
    int i = blockIdx.x*blockDim.x + threadIdx.x;      // 0 .. 524287
    int j = i >> 9, k = i & 511;
    g_Winit[(size_t)j*512 + k] = (j < 512) ? Wih_i[j*512 + k] : Wic_i[(j-512)*512 + k];
    if (i < 1024) g_binit[i] = (i < 512) ? bih_i[i] : bic_i[i-512];
    if (i == 0) g_bar = 0u;
}

__global__ void setup_rowmap(const int* __restrict__ lengths) {
    __shared__ int nt[TMAX+1];
    int tid = threadIdx.x;
    if (tid < TMAX) {
        int n = 0;
        for (int b = 0; b < BB; b++) n += (lengths[b]-1 > tid);
        nt[tid] = n;
    }
    __syncthreads();
    if (tid == 0) {
        int pre = 0;
        for (int t = 0; t < TMAX; t++) { int n = nt[t]; nt[t] = pre; pre += n; }
        nt[TMAX] = pre;
        g_count = pre;
    }
    __syncthreads();
    for (int t = 0; t < TMAX; t++) {
        int base = nt[t];
        int cnt  = nt[t+1] - base;
        for (int b = tid; b < cnt; b += blockDim.x)
            g_rowmap[base + b] = t*64 + b;   // lengths sorted desc -> active b's are a prefix
    }
}

__global__ void zero_inactive(const int* __restrict__ lengths, float* __restrict__ out) {
    int m = blockIdx.x;           // 0..1983
    int t = m >> 6, b = m & 63;
    if (lengths[b]-1 > t) return;
    float4* p = reinterpret_cast<float4*>(out + (size_t)b*(TMAX*VV) + (size_t)t*VV);
    float4 z = make_float4(0,0,0,0);
    for (int i = threadIdx.x; i < VV/4; i += blockDim.x) p[i] = z;
}

// -------------------- mean over L (raw [B,F,L] layout) ----------------------
__global__ void mean_kernel(const float* __restrict__ features) {
    int gw   = (blockIdx.x*blockDim.x + threadIdx.x) >> 5;
    int lane = threadIdx.x & 31;
    if (gw >= BB*FF) return;
    int b = gw >> 9, f = gw & 511;
    const float* p = features + (size_t)b*FL + (size_t)f*LL;
    float s = 0.f;
    for (int l = lane; l < LL; l += 32) s += p[l];
    #pragma unroll
    for (int o = 16; o; o >>= 1) s += __shfl_xor_sync(0xffffffffu, s, o);
    if (lane == 0) g_meanf[gw] = s * (1.f/196.f);
}

// ---- init GEMM: g_hc[0][j][b] = meanf[b] @ Winit[j] + binit[j] (transposed C)
#define BM 64
#define BN 64
#define BK 16
__global__ __launch_bounds__(256)
void gemm_init() {
    __shared__ float As[BM][BK+1];
    __shared__ float Bs[BN][BK+1];
    const int K = 512;
    int bn = blockIdx.x * BN;             // over N=1024
    int tid = threadIdx.x;
    int lr = tid >> 2, lk = (tid & 3) * 4;
    int rm = (tid & 15) * 4, rn = (tid >> 4) * 4;
    float acc[4][4] = {};
    for (int k0 = 0; k0 < K; k0 += BK) {
        float4 av = *reinterpret_cast<const float4*>(g_meanf + (size_t)lr*K + k0 + lk);
        float4 bv = *reinterpret_cast<const float4*>(g_Winit + (size_t)(bn+lr)*K + k0 + lk);
        As[lr][lk+0]=av.x; As[lr][lk+1]=av.y; As[lr][lk+2]=av.z; As[lr][lk+3]=av.w;
        Bs[lr][lk+0]=bv.x; Bs[lr][lk+1]=bv.y; Bs[lr][lk+2]=bv.z; Bs[lr][lk+3]=bv.w;
        __syncthreads();
        #pragma unroll
        for (int kk = 0; kk < BK; kk++) {
            float a[4], bb[4];
            #pragma unroll
            for (int i = 0; i < 4; i++) a[i]  = As[rm+i][kk];
            #pragma unroll
            for (int j = 0; j < 4; j++) bb[j] = Bs[rn+j][kk];
            #pragma unroll
            for (int i = 0; i < 4; i++)
                #pragma unroll
                for (int j = 0; j < 4; j++)
                    acc[i][j] = fmaf(a[i], bb[j], acc[i][j]);
        }
        __syncthreads();
    }
    #pragma unroll
    for (int i = 0; i < 4; i++) {
        int m = rm + i;                    // b
        #pragma unroll
        for (int j = 0; j < 4; j++) {
            int n = bn + rn + j;           // j-index
            g_hc[0][(size_t)n*64 + m] = acc[i][j] + g_binit[n];
        }
    }
}

// -------------------- big double-buffered SGEMM 128x128x8 -------------------
#define GBM 128
#define GBN 128
#define GBK 8
__global__ __launch_bounds__(256, 2)
void gemm128(const float* __restrict__ A, const float* __restrict__ B,
             const float* __restrict__ bias, float* __restrict__ C,
             int M, int N, int K) {
    __shared__ float As[2][GBK][GBM];
    __shared__ float Bs[2][GBK][GBN];
    int bm = blockIdx.y * GBM, bn = blockIdx.x * GBN;
    int tid = threadIdx.x;
    int lrow = tid >> 1;
    int lk   = (tid & 1) * 4;
    int tx = tid & 15, ty = tid >> 4;
    int rm = ty*8, rn = tx*8;
    float acc[8][8] = {};
    float4 aR, bR;
    const float4 Z4 = make_float4(0,0,0,0);
    {
        int ar = bm + lrow, br = bn + lrow;
        aR = (ar < M) ? *reinterpret_cast<const float4*>(A + (size_t)ar*K + lk) : Z4;
        bR = (br < N) ? *reinterpret_cast<const float4*>(B + (size_t)br*K + lk) : Z4;
        As[0][lk+0][lrow]=aR.x; As[0][lk+1][lrow]=aR.y; As[0][lk+2][lrow]=aR.z; As[0][lk+3][lrow]=aR.w;
        Bs[0][lk+0][lrow]=bR.x; Bs[0][lk+1][lrow]=bR.y; Bs[0][lk+2][lrow]=bR.z; Bs[0][lk+3][lrow]=bR.w;
    }
    __syncthreads();
    int buf = 0;
    for (int k0 = GBK; k0 <= K; k0 += GBK) {
        bool more = (k0 < K);
        if (more) {
            int ar = bm + lrow, br = bn + lrow;
            aR = (ar < M) ? *reinterpret_cast<const float4*>(A + (size_t)ar*K + k0 + lk) : Z4;
            bR = (br < N) ? *reinterpret_cast<const float4*>(B + (size_t)br*K + k0 + lk) : Z4;
        }
        #pragma unroll
        for (int kk = 0; kk < GBK; kk++) {
            float a[8], b[8];
            *reinterpret_cast<float4*>(a)   = *reinterpret_cast<const float4*>(&As[buf][kk][rm]);
            *reinterpret_cast<float4*>(a+4) = *reinterpret_cast<const float4*>(&As[buf][kk][rm+4]);
            *reinterpret_cast<float4*>(b)   = *reinterpret_cast<const float4*>(&Bs[buf][kk][rn]);
            *reinterpret_cast<float4*>(b+4) = *reinterpret_cast<const float4*>(&Bs[buf][kk][rn+4]);
            #pragma unroll
            for (int i = 0; i < 8; i++)
                #pragma unroll
                for (int j = 0; j < 8; j++)
                    acc[i][j] = fmaf(a[i], b[j], acc[i][j]);
        }
        if (more) {
            int nb = buf ^ 1;
            As[nb][lk+0][lrow]=aR.x; As[nb][lk+1][lrow]=aR.y; As[nb][lk+2][lrow]=aR.z; As[nb][lk+3][lrow]=aR.w;
            Bs[nb][lk+0][lrow]=bR.x; Bs[nb][lk+1][lrow]=bR.y; Bs[nb][lk+2][lrow]=bR.z; Bs[nb][lk+3][lrow]=bR.w;
        }
        __syncthreads();
        buf ^= 1;
    }
    #pragma unroll
    for (int i = 0; i < 8; i++) {
        int m = bm + rm + i;
        if (m >= M) continue;
        float* crow = C + (size_t)m*N;
        #pragma unroll
        for (int j = 0; j < 8; j++) {
            int n = bn + rn + j;
            if (n < N) crow[n] = acc[i][j] + (bias ? bias[n] : 0.f);
        }
    }
}

// ------ preds GEMM on compacted active rows (A rows via g_rowmap -> g_Hs) ---
__global__ __launch_bounds__(256, 2)
void gemm_preds_c(const float* __restrict__ B, const float* __restrict__ bias,
                  float* __restrict__ out) {
    __shared__ float As[2][GBK][GBM];
    __shared__ float Bs[2][GBK][GBN];
    const int N = VV, K = HH;
    int count = g_count;
    int bm = blockIdx.y * GBM, bn = blockIdx.x * GBN;
    if (bm >= count) return;
    int tid = threadIdx.x;
    int lrow = tid >> 1;
    int lk   = (tid & 1) * 4;
    int tx = tid & 15, ty = tid >> 4;
    int rm = ty*8, rn = tx*8;
    float acc[8][8] = {};
    float4 aR, bR;
    const float4 Z4 = make_float4(0,0,0,0);
    int arow_m = (bm + lrow < count) ? g_rowmap[bm + lrow] : -1;
    {
        int br = bn + lrow;
        aR = (arow_m >= 0) ? *reinterpret_cast<const float4*>(g_Hs + (size_t)arow_m*K + lk) : Z4;
        bR = (br < N)      ? *reinterpret_cast<const float4*>(B + (size_t)br*K + lk) : Z4;
        As[0][lk+0][lrow]=aR.x; As[0][lk+1][lrow]=aR.y; As[0][lk+2][lrow]=aR.z; As[0][lk+3][lrow]=aR.w;
        Bs[0][lk+0][lrow]=bR.x; Bs[0][lk+1][lrow]=bR.y; Bs[0][lk+2][lrow]=bR.z; Bs[0][lk+3][lrow]=bR.w;
    }
    __syncthreads();
    int buf = 0;
    for (int k0 = GBK; k0 <= K; k0 += GBK) {
        bool more = (k0 < K);
        if (more) {
            int br = bn + lrow;
            aR = (arow_m >= 0) ? *reinterpret_cast<const float4*>(g_Hs + (size_t)arow_m*K + k0 + lk) : Z4;
            bR = (br < N)      ? *reinterpret_cast<const float4*>(B + (size_t)br*K + k0 + lk) : Z4;
        }
        #pragma unroll
        for (int kk = 0; kk < GBK; kk++) {
            float a[8], b[8];
            *reinterpret_cast<float4*>(a)   = *reinterpret_cast<const float4*>(&As[buf][kk][rm]);
            *reinterpret_cast<float4*>(a+4) = *reinterpret_cast<const float4*>(&As[buf][kk][rm+4]);
            *reinterpret_cast<float4*>(b)   = *reinterpret_cast<const float4*>(&Bs[buf][kk][rn]);
            *reinterpret_cast<float4*>(b+4) = *reinterpret_cast<const float4*>(&Bs[buf][kk][rn+4]);
            #pragma unroll
            for (int i = 0; i < 8; i++)
                #pragma unroll
                for (int j = 0; j < 8; j++)
                    acc[i][j] = fmaf(a[i], b[j], acc[i][j]);
        }
        if (more) {
            int nb = buf ^ 1;
            As[nb][lk+0][lrow]=aR.x; As[nb][lk+1][lrow]=aR.y; As[nb][lk+2][lrow]=aR.z; As[nb][lk+3][lrow]=aR.w;
            Bs[nb][lk+0][lrow]=bR.x; Bs[nb][lk+1][lrow]=bR.y; Bs[nb][lk+2][lrow]=bR.z; Bs[nb][lk+3][lrow]=bR.w;
        }
        __syncthreads();
        buf ^= 1;
    }
    #pragma unroll
    for (int i = 0; i < 8; i++) {
        int r = bm + rm + i;
        if (r >= count) continue;
        int m = g_rowmap[r];
        int t_ = m >> 6, b_ = m & 63;
        float* crow = out + (size_t)b_*(TMAX*VV) + (size_t)t_*VV;
        #pragma unroll
        for (int j = 0; j < 8; j++) {
            int n = bn + rn + j;
            if (n < N) crow[n] = acc[i][j] + bias[n];
        }
    }
}

// ============ persistent recurrence kernel (whole 31-step loop) ==============
__global__ __launch_bounds__(256)
void recurrence(const float* __restrict__ features,
                const float* __restrict__ W_dec, const float* __restrict__ b_dec,
                const float* __restrict__ W_fb,  const float* __restrict__ b_fb,
                const float* __restrict__ W_full,
                const float* __restrict__ W_emb,
                const int*   __restrict__ captions,
                const int*   __restrict__ lengths,
                const float* __restrict__ W_ih, const float* __restrict__ W_hh,
                const float* __restrict__ b_ih, const float* __restrict__ b_hh,
                float* __restrict__ alphas_out)
{
    const int blk = blockIdx.x, tid = threadIdx.x;
    __shared__ float hs[64][64];            // P1 h chunk [kk][b]
    __shared__ float sc[200], red[8];       // P2
    __shared__ float As2[2][16][68];        // P3 A tiles (double-buffered) [kk][b]
    __shared__ float Bs2[2][16][17];        // P3 W tiles (double-buffered) [k][col]
    __shared__ float gs[16][65];            // P3 gates  [col][b]
    unsigned ep = 0;

    for (int t = 0; t < TMAX; t++) {
        const int p = t & 1;

        // ---------------- P1: de/fbeta projection (blocks 0..127) ------------
        if (blk < 128) {
            const bool isdec = (blk < 64);
            const int j = (blk & 63) * 8 + (tid >> 5);     // warp -> one j row
            const int lane = tid & 31;
            const float* wrow = (isdec ? W_dec : W_fb) + (size_t)j * 512;
            const float* hb   = g_hc[p];
            float acc0 = 0.f, acc1 = 0.f;
            float4 hv[4];
            #pragma unroll
            for (int r = 0; r < 4; r++) {
                int idx = tid + r*256;
                int kk = idx >> 4, b4 = (idx & 15) * 4;
                hv[r] = __ldcg(reinterpret_cast<const float4*>(hb + (size_t)kk*64 + b4));
            }
            for (int c = 0; c < 8; c++) {
                #pragma unroll
                for (int r = 0; r < 4; r++) {
                    int idx = tid + r*256;
                    int kk = idx >> 4, b4 = (idx & 15) * 4;
                    *reinterpret_cast<float4*>(&hs[kk][b4]) = hv[r];
                }
                if (c < 7) {
                    #pragma unroll
                    for (int r = 0; r < 4; r++) {
                        int idx = tid + r*256;
                        int kk = idx >> 4, b4 = (idx & 15) * 4;
                        hv[r] = __ldcg(reinterpret_cast<const float4*>(hb + (size_t)((c+1)*64 + kk)*64 + b4));
                    }
                }
                __syncthreads();
                int k0 = c * 64;
                #pragma unroll 8
                for (int kk = 0; kk < 64; kk++) {
                    float w = __ldg(wrow + k0 + kk);
                    acc0 = fmaf(w, hs[kk][lane],      acc0);
                    acc1 = fmaf(w, hs[kk][lane + 32], acc1);
                }
                __syncthreads();
            }
            float bj = isdec ? b_dec[j] : b_fb[j];
            if (isdec) {
                __stcg(&g_defb[lane*1024 + j],        acc0 + bj);
                __stcg(&g_defb[(lane+32)*1024 + j],   acc1 + bj);
            } else {
                __stcg(&g_defb[lane*1024 + 512 + j],      fsigm(acc0 + bj));
                __stcg(&g_defb[(lane+32)*1024 + 512 + j], fsigm(acc1 + bj));
            }
        }
        ep++; grid_bar(ep * NB);

        // ---------------- P2: attention + softmax + z + emb (blocks 0..63) ---
        if (blk < 64) {
            const int b = blk;
            const int lane = tid & 31, wid = tid >> 5;

            // hoist de + W_full into registers (a = lane + 32k)
            float der[16], wr[16];
            #pragma unroll
            for (int k = 0; k < 16; k++) {
                der[k] = __ldcg(&g_defb[b*1024 + lane + 32*k]);
                wr[k]  = __ldg(&W_full[lane + 32*k]);
            }

            for (int l = wid; l < LL; l += 8) {
                const float* ea = g_enatt + ((size_t)b*LL + l)*AA + lane;
                float s = 0.f;
                #pragma unroll
                for (int k = 0; k < 16; k++)
                    s += ftanh_a(__ldg(ea + 32*k) + der[k]) * wr[k];
                #pragma unroll
                for (int o = 16; o; o >>= 1) s += __shfl_xor_sync(0xffffffffu, s, o);
                if (lane == 0) sc[l] = s;
            }
            __syncthreads();

            float mx = -1e30f;
            for (int l = tid; l < LL; l += 256) mx = fmaxf(mx, sc[l]);
            #pragma unroll
            for (int o = 16; o; o >>= 1) mx = fmaxf(mx, __shfl_xor_sync(0xffffffffu, mx, o));
            if (lane == 0) red[wid] = mx;
            __syncthreads();
            if (wid == 0) {
                float v = (lane < 8) ? red[lane] : -1e30f;
                #pragma unroll
                for (int o = 4; o; o >>= 1) v = fmaxf(v, __shfl_xor_sync(0xffffffffu, v, o));
                if (lane == 0) red[0] = v;
            }
            __syncthreads();
            mx = red[0];
            __syncthreads();

            float sum = 0.f;
            for (int l = tid; l < LL; l += 256) {
                float e = __expf(sc[l] - mx);
                sc[l] = e;
                sum += e;
            }
            #pragma unroll
            for (int o = 16; o; o >>= 1) sum += __shfl_xor_sync(0xffffffffu, sum, o);
            if (lane == 0) red[wid] = sum;
            __syncthreads();
            if (wid == 0) {
                float v = (lane < 8) ? red[lane] : 0.f;
                #pragma unroll
                for (int o = 4; o; o >>= 1) v += __shfl_xor_sync(0xffffffffu, v, o);
                if (lane == 0) red[0] = v;
            }
            __syncthreads();
            float inv = __fdividef(1.f, red[0]);

            bool active = (lengths[b] - 1) > t;
            for (int l = tid; l < LL; l += 256)
                alphas_out[(size_t)b*(TMAX*LL) + (size_t)t*LL + l] = active ? sc[l]*inv : 0.f;

            // z = (alpha @ feat_r[b]) * sigm(fbeta) -> xT[512+f][b]  (4-way acc)
            const float* fbb = features + (size_t)b*FL;
            for (int f = tid; f < FF; f += 256) {
                float z0=0.f, z1=0.f, z2=0.f, z3=0.f;
                #pragma unroll 4
                for (int l = 0; l < 196; l += 4) {
                    z0 = fmaf(sc[l+0], __ldg(fbb + (size_t)(l+0)*FF + f), z0);
                    z1 = fmaf(sc[l+1], __ldg(fbb + (size_t)(l+1)*FF + f), z1);
                    z2 = fmaf(sc[l+2], __ldg(fbb + (size_t)(l+2)*FF + f), z2);
                    z3 = fmaf(sc[l+3], __ldg(fbb + (size_t)(l+3)*FF + f), z3);
                }
                float z = (z0 + z1) + (z2 + z3);
                float gate = __ldcg(&g_defb[b*1024 + 512 + f]);
                __stcg(&g_xT[(size_t)(512+f)*64 + b], z * inv * gate);
            }
            // embedding -> xT[e][b]
            int cap = captions[b*TT + t];
            for (int e = tid; e < EE; e += 256)
                __stcg(&g_xT[(size_t)e*64 + b], __ldg(&W_emb[(size_t)cap*EE + e]));
        }
        ep++; grid_bar(ep * NB);

        // ------- P3: gates GEMM + LSTM cell, pipelined (blocks 0..127) -------
        if (blk < 128) {
            const int txx = tid & 15, tyy = tid >> 4;
            float acc[4] = {0,0,0,0};
            const int gcol_c = (txx >> 2)*512 + blk*4 + (txx & 3);
            const int kk_a = tid >> 4, b4 = (tid & 15) * 4;
            const int cB = tid >> 2, k4 = (tid & 3) * 4;
            const int gcol_l = (cB >> 2)*512 + blk*4 + (cB & 3);

            // flattened 96 tiles: [0,64) over g_xT/W_ih (K=1024), [64,96) over g_hc/W_hh (K=512)
            auto ptrA = [&](int kt) -> const float4* {
                const float* Ab = (kt < 64) ? g_xT : g_hc[p];
                int k0 = (kt < 64) ? kt*16 : (kt-64)*16;
                return reinterpret_cast<const float4*>(Ab + (size_t)(k0 + kk_a)*64 + b4);
            };
            auto ptrW = [&](int kt) -> const float4* {
                const float* Wb = (kt < 64) ? W_ih : W_hh;
                int ws = (kt < 64) ? 1024 : 512;
                int k0 = (kt < 64) ? kt*16 : (kt-64)*16;
                return reinterpret_cast<const float4*>(Wb + (size_t)gcol_l*ws + k0 + k4);
            };

            float4 avp = __ldcg(ptrA(0));
            float4 wvp = make_float4(0,0,0,0);
            if (tid < 64) wvp = *ptrW(0);
            *reinterpret_cast<float4*>(&As2[0][kk_a][b4]) = avp;
            if (tid < 64) {
                Bs2[0][k4+0][cB]=wvp.x; Bs2[0][k4+1][cB]=wvp.y;
                Bs2[0][k4+2][cB]=wvp.z; Bs2[0][k4+3][cB]=wvp.w;
            }
            __syncthreads();

            for (int kt = 0; kt < 96; kt++) {
                const int cur = kt & 1;
                const bool more = (kt + 1 < 96);
                if (more) {
                    avp = __ldcg(ptrA(kt+1));
                    if (tid < 64) wvp = *ptrW(kt+1);
                }
                #pragma unroll
                for (int kk = 0; kk < 16; kk++) {
                    float bval = Bs2[cur][kk][txx];
                    #pragma unroll
                    for (int i = 0; i < 4; i++)
                        acc[i] = fmaf(As2[cur][kk][tyy*4 + i], bval, acc[i]);
                }
                if (more) {
                    const int nxt = cur ^ 1;
                    *reinterpret_cast<float4*>(&As2[nxt][kk_a][b4]) = avp;
                    if (tid < 64) {
                        Bs2[nxt][k4+0][cB]=wvp.x; Bs2[nxt][k4+1][cB]=wvp.y;
                        Bs2[nxt][k4+2][cB]=wvp.z; Bs2[nxt][k4+3][cB]=wvp.w;
                    }
                }
                __syncthreads();
            }

            float bsum = b_ih[gcol_c] + b_hh[gcol_c];
            #pragma unroll
            for (int i = 0; i < 4; i++) gs[txx][tyy*4 + i] = acc[i] + bsum;
            __syncthreads();

            // cell update: 256 threads = 64 b x 4 local j
            int b  = tid & 63;
            int jl = tid >> 6;
            int j  = blk*4 + jl;
            float gi = gs[ 0 + jl][b];
            float gf = gs[ 4 + jl][b];
            float gg = gs[ 8 + jl][b];
            float go = gs[12 + jl][b];
            float h_old = __ldcg(&g_hc[p][(size_t)j*64 + b]);
            float c_old = __ldcg(&g_hc[p][(size_t)(512+j)*64 + b]);
            float cn = fsigm(gf)*c_old + fsigm(gi)*ftanh_e(gg);
            float hn = fsigm(go)*ftanh_e(cn);
            g_Hs[(size_t)t*(BB*HH) + b*HH + j] = hn;
            bool act = (lengths[b] - 1) > t;
            __stcg(&g_hc[p^1][(size_t)j*64 + b],       act ? hn : h_old);
            __stcg(&g_hc[p^1][(size_t)(512+j)*64 + b], act ? cn : c_old);
            __syncthreads();
        }
        ep++; grid_bar(ep * NB);
    }
}

// -------------------- host launcher -----------------------------------------
extern "C" void kernel_launch(void* const* d_in, const int* in_sizes, int n_in,
                              void* d_out, int out_size) {
    const float* features = (const float*)d_in[0];
    const int*   captions = (const int*)  d_in[1];
    const int*   lengths  = (const int*)  d_in[2];
    const float* W_emb    = (const float*)d_in[3];
    const float* W_enc    = (const float*)d_in[4];
    const float* b_enc    = (const float*)d_in[5];
    const float* W_dec    = (const float*)d_in[6];
    const float* b_dec    = (const float*)d_in[7];
    const float* W_full   = (const float*)d_in[8];
    /* b_full (d_in[9]) softmax-invariant: unused */
    const float* W_fbeta  = (const float*)d_in[10];
    const float* b_fbeta  = (const float*)d_in[11];
    const float* W_ih     = (const float*)d_in[12];
    const float* W_hh     = (const float*)d_in[13];
    const float* b_ih     = (const float*)d_in[14];
    const float* b_hh     = (const float*)d_in[15];
    const float* W_out    = (const float*)d_in[16];
    const float* b_out    = (const float*)d_in[17];
    const float* W_init_h = (const float*)d_in[18];
    const float* b_init_h = (const float*)d_in[19];
    const float* W_init_c = (const float*)d_in[20];
    const float* b_init_c = (const float*)d_in[21];

    float* out = (float*)d_out;
    float* alphas_out = out + (size_t)BB*TMAX*VV;

    (void)n_in; (void)in_sizes; (void)out_size;

    // device address of g_enatt for the generic GEMM (host symbol != device addr!)
    float* p_enatt;
    cudaGetSymbolAddress((void**)&p_enatt, g_enatt);

    // one-time setup (also resets the grid-barrier counter every launch/replay)
    setup_all<<<2048, 256>>>(W_init_h, b_init_h, W_init_c, b_init_c);
    setup_rowmap<<<1, 256>>>(lengths);
    zero_inactive<<<TMAX*BB, 256>>>(lengths, out);

    // en_att = feat_r @ W_enc^T + b_enc   (M=12544, N=512, K=512)
    {
        dim3 g(AA/GBN, ENATT_M/GBM);   // (4, 98)
        gemm128<<<g, 256>>>(features, W_enc, b_enc, p_enatt, ENATT_M, AA, FF);
    }

    // mean over L, then combined transposed [h0|c0] init GEMM
    mean_kernel<<<(BB*FF*32 + 255)/256, 256>>>(features);
    gemm_init<<<16, 256>>>();

    // whole recurrence in ONE persistent kernel (grid <= SM count)
    recurrence<<<NB, 256>>>(features, W_dec, b_dec, W_fbeta, b_fbeta, W_full,
                            W_emb, captions, lengths, W_ih, W_hh, b_ih, b_hh,
                            alphas_out);

    // compacted output projection (active rows only)
    {
        dim3 g((VV + GBN - 1)/GBN, (TMAX*BB + GBM - 1)/GBM);  // (79, 16)
        gemm_preds_c<<<g, 256>>>(W_out, b_out, out);
    }
}

// round 15
// speedup vs baseline: 1.9721x; 1.4413x over previous
#include <cuda_runtime.h>
#include <cuda_bf16.h>
#include <math.h>

// Problem constants
#define BB   64
#define TT   32
#define TMAX 31
#define FF   512
#define LL   196
#define EE   512
#define HH   512
#define AA   512
#define VV   10000

#define FL   (FF*LL)        // 100352
#define ENATT_M (BB*LL)     // 12544
#define NB   128            // persistent grid size (<= SM count -> co-resident)

// -------------------- scratch (static device globals; no allocs) ------------
__device__ float g_enatt[BB*LL*AA];        // 25.7 MB
__device__ float g_meanf[BB*FF];
__device__ float g_hc[2][1024*BB];         // TRANSPOSED: [j*64+b]; j<512 = h_j, j>=512 = c_{j-512}
__device__ float g_xT[1024*BB];            // TRANSPOSED x: [j*64+b]; j<512 emb, j>=512 z
__device__ float g_defb[BB*1024];          // [b][j]; j<512 de, j>=512 sigm(fbeta)
__device__ float g_Hs[TMAX*BB*HH];         // row-major rows m=t*64+b (A of preds GEMM)
__device__ float g_Winit[1024*512];        // concat [W_init_h; W_init_c]
__device__ float g_binit[1024];
__device__ int   g_rowmap[TMAX*BB];
__device__ int   g_count;
__device__ unsigned g_bar;                 // software grid-barrier counter

// -------------------- fast math helpers -------------------------------------
__device__ __forceinline__ float fsigm(float x) {
    float e = __expf(fminf(-x, 30.f));
    return __fdividef(1.f, 1.f + e);
}
__device__ __forceinline__ float ftanh_e(float x) {     // accurate-ish (cell state)
    x = fminf(fmaxf(x, -15.f), 15.f);
    float e = __expf(2.f*x);
    return __fdividef(e - 1.f, e + 1.f);
}
__device__ __forceinline__ float ftanh_a(float x) {     // 1-MUFU approx (scores only)
    float r; asm("tanh.approx.f32 %0, %1;" : "=f"(r) : "f"(x)); return r;
}

// ------- software grid barrier: atomic arrive, LD.CG poll (no RMW storm) -----
__device__ __forceinline__ void grid_bar(unsigned target) {
    __syncthreads();
    if (threadIdx.x == 0) {
        __threadfence();                       // release: drain my stcg writes
        atomicAdd(&g_bar, 1u);
        unsigned v;
        for (;;) {
            asm volatile("ld.global.cg.u32 %0, [%1];" : "=r"(v) : "l"(&g_bar) : "memory");
            if (v >= target) break;
            __nanosleep(32);
        }
        __threadfence();                       // acquire: order subsequent ldcg reads
    }
    __syncthreads();
}

// ------ merged setup: Winit/binit/g_bar reset + mean over L ------------------
__global__ void setup_init(const float* __restrict__ Wih_i, const float* __restrict__ bih_i,
                           const float* __restrict__ Wic_i, const float* __restrict__ bic_i,
                           const float* __restrict__ features) {
    int blk = blockIdx.x, tid = threadIdx.x;
    if (blk < 2048) {
        int i = blk*256 + tid;                 // 0 .. 524287
        int j = i >> 9, k = i & 511;
        g_Winit[(size_t)j*512 + k] = (j < 512) ? Wih_i[j*512 + k] : Wic_i[(j-512)*512 + k];
        if (i < 1024) g_binit[i] = (i < 512) ? bih_i[i] : bic_i[i-512];
        if (i == 0) g_bar = 0u;
    } else {
        int gw   = ((blk-2048)*256 + tid) >> 5;    // 0 .. 32767
        int lane = tid & 31;
        if (gw >= BB*FF) return;
        int b = gw >> 9, f = gw & 511;
        const float* p = features + (size_t)b*FL + (size_t)f*LL;
        float s = 0.f;
        for (int l = lane; l < LL; l += 32) s += p[l];
        #pragma unroll
        for (int o = 16; o; o >>= 1) s += __shfl_xor_sync(0xffffffffu, s, o);
        if (lane == 0) g_meanf[gw] = s * (1.f/196.f);
    }
}

__global__ void setup_rowmap(const int* __restrict__ lengths) {
    __shared__ int nt[TMAX+1];
    int tid = threadIdx.x;
    if (tid < TMAX) {
        int n = 0;
        for (int b = 0; b < BB; b++) n += (lengths[b]-1 > tid);
        nt[tid] = n;
    }
    __syncthreads();
    if (tid == 0) {
        int pre = 0;
        for (int t = 0; t < TMAX; t++) { int n = nt[t]; nt[t] = pre; pre += n; }
        nt[TMAX] = pre;
        g_count = pre;
    }
    __syncthreads();
    for (int t = 0; t < TMAX; t++) {
        int base = nt[t];
        int cnt  = nt[t+1] - base;
        for (int b = tid; b < cnt; b += blockDim.x)
            g_rowmap[base + b] = t*64 + b;   // lengths sorted desc -> active b's are a prefix
    }
}

__global__ void zero_inactive(const int* __restrict__ lengths, float* __restrict__ out) {
    int m = blockIdx.x;           // 0..1983
    int t = m >> 6, b = m & 63;
    if (lengths[b]-1 > t) return;
    float4* p = reinterpret_cast<float4*>(out + (size_t)b*(TMAX*VV) + (size_t)t*VV);
    float4 z = make_float4(0,0,0,0);
    for (int i = threadIdx.x; i < VV/4; i += blockDim.x) p[i] = z;
}

// ---- init GEMM: g_hc[0][j][b] = meanf[b] @ Winit[j] + binit[j] (transposed C)
#define BM 64
#define BN 64
#define BK 16
__global__ __launch_bounds__(256)
void gemm_init() {
    __shared__ float As[BM][BK+1];
    __shared__ float Bs[BN][BK+1];
    const int K = 512;
    int bn = blockIdx.x * BN;             // over N=1024
    int tid = threadIdx.x;
    int lr = tid >> 2, lk = (tid & 3) * 4;
    int rm = (tid & 15) * 4, rn = (tid >> 4) * 4;
    float acc[4][4] = {};
    for (int k0 = 0; k0 < K; k0 += BK) {
        float4 av = *reinterpret_cast<const float4*>(g_meanf + (size_t)lr*K + k0 + lk);
        float4 bv = *reinterpret_cast<const float4*>(g_Winit + (size_t)(bn+lr)*K + k0 + lk);
        As[lr][lk+0]=av.x; As[lr][lk+1]=av.y; As[lr][lk+2]=av.z; As[lr][lk+3]=av.w;
        Bs[lr][lk+0]=bv.x; Bs[lr][lk+1]=bv.y; Bs[lr][lk+2]=bv.z; Bs[lr][lk+3]=bv.w;
        __syncthreads();
        #pragma unroll
        for (int kk = 0; kk < BK; kk++) {
            float a[4], bb[4];
            #pragma unroll
            for (int i = 0; i < 4; i++) a[i]  = As[rm+i][kk];
            #pragma unroll
            for (int j = 0; j < 4; j++) bb[j] = Bs[rn+j][kk];
            #pragma unroll
            for (int i = 0; i < 4; i++)
                #pragma unroll
                for (int j = 0; j < 4; j++)
                    acc[i][j] = fmaf(a[i], bb[j], acc[i][j]);
        }
        __syncthreads();
    }
    #pragma unroll
    for (int i = 0; i < 4; i++) {
        int m = rm + i;                    // b
        #pragma unroll
        for (int j = 0; j < 4; j++) {
            int n = bn + rn + j;           // j-index
            g_hc[0][(size_t)n*64 + m] = acc[i][j] + g_binit[n];
        }
    }
}

// -------------------- big double-buffered SGEMM 128x128x8 -------------------
#define GBM 128
#define GBN 128
#define GBK 8
__global__ __launch_bounds__(256, 2)
void gemm128(const float* __restrict__ A, const float* __restrict__ B,
             const float* __restrict__ bias, float* __restrict__ C,
             int M, int N, int K) {
    __shared__ float As[2][GBK][GBM];
    __shared__ float Bs[2][GBK][GBN];
    int bm = blockIdx.y * GBM, bn = blockIdx.x * GBN;
    int tid = threadIdx.x;
    int lrow = tid >> 1;
    int lk   = (tid & 1) * 4;
    int tx = tid & 15, ty = tid >> 4;
    int rm = ty*8, rn = tx*8;
    float acc[8][8] = {};
    float4 aR, bR;
    const float4 Z4 = make_float4(0,0,0,0);
    {
        int ar = bm + lrow, br = bn + lrow;
        aR = (ar < M) ? *reinterpret_cast<const float4*>(A + (size_t)ar*K + lk) : Z4;
        bR = (br < N) ? *reinterpret_cast<const float4*>(B + (size_t)br*K + lk) : Z4;
        As[0][lk+0][lrow]=aR.x; As[0][lk+1][lrow]=aR.y; As[0][lk+2][lrow]=aR.z; As[0][lk+3][lrow]=aR.w;
        Bs[0][lk+0][lrow]=bR.x; Bs[0][lk+1][lrow]=bR.y; Bs[0][lk+2][lrow]=bR.z; Bs[0][lk+3][lrow]=bR.w;
    }
    __syncthreads();
    int buf = 0;
    for (int k0 = GBK; k0 <= K; k0 += GBK) {
        bool more = (k0 < K);
        if (more) {
            int ar = bm + lrow, br = bn + lrow;
            aR = (ar < M) ? *reinterpret_cast<const float4*>(A + (size_t)ar*K + k0 + lk) : Z4;
            bR = (br < N) ? *reinterpret_cast<const float4*>(B + (size_t)br*K + k0 + lk) : Z4;
        }
        #pragma unroll
        for (int kk = 0; kk < GBK; kk++) {
            float a[8], b[8];
            *reinterpret_cast<float4*>(a)   = *reinterpret_cast<const float4*>(&As[buf][kk][rm]);
            *reinterpret_cast<float4*>(a+4) = *reinterpret_cast<const float4*>(&As[buf][kk][rm+4]);
            *reinterpret_cast<float4*>(b)   = *reinterpret_cast<const float4*>(&Bs[buf][kk][rn]);
            *reinterpret_cast<float4*>(b+4) = *reinterpret_cast<const float4*>(&Bs[buf][kk][rn+4]);
            #pragma unroll
            for (int i = 0; i < 8; i++)
                #pragma unroll
                for (int j = 0; j < 8; j++)
                    acc[i][j] = fmaf(a[i], b[j], acc[i][j]);
        }
        if (more) {
            int nb = buf ^ 1;
            As[nb][lk+0][lrow]=aR.x; As[nb][lk+1][lrow]=aR.y; As[nb][lk+2][lrow]=aR.z; As[nb][lk+3][lrow]=aR.w;
            Bs[nb][lk+0][lrow]=bR.x; Bs[nb][lk+1][lrow]=bR.y; Bs[nb][lk+2][lrow]=bR.z; Bs[nb][lk+3][lrow]=bR.w;
        }
        __syncthreads();
        buf ^= 1;
    }
    #pragma unroll
    for (int i = 0; i < 8; i++) {
        int m = bm + rm + i;
        if (m >= M) continue;
        float* crow = C + (size_t)m*N;
        #pragma unroll
        for (int j = 0; j < 8; j++) {
            int n = bn + rn + j;
            if (n < N) crow[n] = acc[i][j] + (bias ? bias[n] : 0.f);
        }
    }
}

// ------ preds GEMM on compacted active rows (A rows via g_rowmap -> g_Hs) ---
__global__ __launch_bounds__(256, 2)
void gemm_preds_c(const float* __restrict__ B, const float* __restrict__ bias,
                  float* __restrict__ out) {
    __shared__ float As[2][GBK][GBM];
    __shared__ float Bs[2][GBK][GBN];
    const int N = VV, K = HH;
    int count = g_count;
    int bm = blockIdx.y * GBM, bn = blockIdx.x * GBN;
    if (bm >= count) return;
    int tid = threadIdx.x;
    int lrow = tid >> 1;
    int lk   = (tid & 1) * 4;
    int tx = tid & 15, ty = tid >> 4;
    int rm = ty*8, rn = tx*8;
    float acc[8][8] = {};
    float4 aR, bR;
    const float4 Z4 = make_float4(0,0,0,0);
    int arow_m = (bm + lrow < count) ? g_rowmap[bm + lrow] : -1;
    {
        int br = bn + lrow;
        aR = (arow_m >= 0) ? *reinterpret_cast<const float4*>(g_Hs + (size_t)arow_m*K + lk) : Z4;
        bR = (br < N)      ? *reinterpret_cast<const float4*>(B + (size_t)br*K + lk) : Z4;
        As[0][lk+0][lrow]=aR.x; As[0][lk+1][lrow]=aR.y; As[0][lk+2][lrow]=aR.z; As[0][lk+3][lrow]=aR.w;
        Bs[0][lk+0][lrow]=bR.x; Bs[0][lk+1][lrow]=bR.y; Bs[0][lk+2][lrow]=bR.z; Bs[0][lk+3][lrow]=bR.w;
    }
    __syncthreads();
    int buf = 0;
    for (int k0 = GBK; k0 <= K; k0 += GBK) {
        bool more = (k0 < K);
        if (more) {
            int br = bn + lrow;
            aR = (arow_m >= 0) ? *reinterpret_cast<const float4*>(g_Hs + (size_t)arow_m*K + k0 + lk) : Z4;
            bR = (br < N)      ? *reinterpret_cast<const float4*>(B + (size_t)br*K + k0 + lk) : Z4;
        }
        #pragma unroll
        for (int kk = 0; kk < GBK; kk++) {
            float a[8], b[8];
            *reinterpret_cast<float4*>(a)   = *reinterpret_cast<const float4*>(&As[buf][kk][rm]);
            *reinterpret_cast<float4*>(a+4) = *reinterpret_cast<const float4*>(&As[buf][kk][rm+4]);
            *reinterpret_cast<float4*>(b)   = *reinterpret_cast<const float4*>(&Bs[buf][kk][rn]);
            *reinterpret_cast<float4*>(b+4) = *reinterpret_cast<const float4*>(&Bs[buf][kk][rn+4]);
            #pragma unroll
            for (int i = 0; i < 8; i++)
                #pragma unroll
                for (int j = 0; j < 8; j++)
                    acc[i][j] = fmaf(a[i], b[j], acc[i][j]);
        }
        if (more) {
            int nb = buf ^ 1;
            As[nb][lk+0][lrow]=aR.x; As[nb][lk+1][lrow]=aR.y; As[nb][lk+2][lrow]=aR.z; As[nb][lk+3][lrow]=aR.w;
            Bs[nb][lk+0][lrow]=bR.x; Bs[nb][lk+1][lrow]=bR.y; Bs[nb][lk+2][lrow]=bR.z; Bs[nb][lk+3][lrow]=bR.w;
        }
        __syncthreads();
        buf ^= 1;
    }
    #pragma unroll
    for (int i = 0; i < 8; i++) {
        int r = bm + rm + i;
        if (r >= count) continue;
        int m = g_rowmap[r];
        int t_ = m >> 6, b_ = m & 63;
        float* crow = out + (size_t)b_*(TMAX*VV) + (size_t)t_*VV;
        #pragma unroll
        for (int j = 0; j < 8; j++) {
            int n = bn + rn + j;
            if (n < N) crow[n] = acc[i][j] + bias[n];
        }
    }
}

// ====== persistent recurrence kernel (31 steps), 512 threads/CTA =============
__global__ __launch_bounds__(512)
void recurrence(const float* __restrict__ features,
                const float* __restrict__ W_dec, const float* __restrict__ b_dec,
                const float* __restrict__ W_fb,  const float* __restrict__ b_fb,
                const float* __restrict__ W_full,
                const float* __restrict__ W_emb,
                const int*   __restrict__ captions,
                const int*   __restrict__ lengths,
                const float* __restrict__ W_ih, const float* __restrict__ W_hh,
                const float* __restrict__ b_ih, const float* __restrict__ b_hh,
                float* __restrict__ alphas_out)
{
    const int blk = blockIdx.x, tid = threadIdx.x;
    __shared__ float hs[64][64];            // P1 h chunk [kk][b]
    __shared__ float sc[200], red[16];      // P2
    __shared__ float As3[2][2][16][68];     // P3 A tiles [group][buf][kk][b]
    __shared__ float Bs3[2][2][16][17];     // P3 W tiles [group][buf][k][col]
    __shared__ float gsA[16][65], gsB[16][65];  // P3 partial gates per K-group
    unsigned ep = 0;

    for (int t = 0; t < TMAX; t++) {
        const int p = t & 1;

        // -------- P1: de/fbeta projection (128 blocks, 2 warps per j) --------
        {
            const int w = tid >> 5, lane = tid & 31;
            const int j = blk*8 + (w >> 1);            // 0..1023
            const int bh = (w & 1) * 32;               // b-half
            const float* wrow = (j < 512) ? (W_dec + (size_t)j*512)
                                          : (W_fb + (size_t)(j-512)*512);
            const float* hb = g_hc[p];
            float acc = 0.f;
            float4 hv[2];
            #pragma unroll
            for (int r = 0; r < 2; r++) {
                int idx = tid + r*512;
                int kk = idx >> 4, b4 = (idx & 15) * 4;
                hv[r] = __ldcg(reinterpret_cast<const float4*>(hb + (size_t)kk*64 + b4));
            }
            for (int c = 0; c < 8; c++) {
                #pragma unroll
                for (int r = 0; r < 2; r++) {
                    int idx = tid + r*512;
                    int kk = idx >> 4, b4 = (idx & 15) * 4;
                    *reinterpret_cast<float4*>(&hs[kk][b4]) = hv[r];
                }
                if (c < 7) {
                    #pragma unroll
                    for (int r = 0; r < 2; r++) {
                        int idx = tid + r*512;
                        int kk = idx >> 4, b4 = (idx & 15) * 4;
                        hv[r] = __ldcg(reinterpret_cast<const float4*>(hb + (size_t)((c+1)*64 + kk)*64 + b4));
                    }
                }
                __syncthreads();
                int k0 = c * 64;
                #pragma unroll 8
                for (int kk = 0; kk < 64; kk++)
                    acc = fmaf(__ldg(wrow + k0 + kk), hs[kk][lane + bh], acc);
                __syncthreads();
            }
            float bj = (j < 512) ? b_dec[j] : b_fb[j-512];
            float v = acc + bj;
            if (j >= 512) v = fsigm(v);
            __stcg(&g_defb[(size_t)(lane + bh)*1024 + j], v);
        }
        ep++; grid_bar(ep * NB);

        // -------- P2: attention + softmax + z + emb (blocks 0..63) -----------
        if (blk < 64) {
            const int b = blk;
            const int lane = tid & 31, wid = tid >> 5;   // 16 warps

            float der[16], wr[16];
            #pragma unroll
            for (int k = 0; k < 16; k++) {
                der[k] = __ldcg(&g_defb[b*1024 + lane + 32*k]);
                wr[k]  = __ldg(&W_full[lane + 32*k]);
            }

            for (int l = wid; l < LL; l += 16) {
                const float* ea = g_enatt + ((size_t)b*LL + l)*AA + lane;
                float s = 0.f;
                #pragma unroll
                for (int k = 0; k < 16; k++)
                    s += ftanh_a(__ldg(ea + 32*k) + der[k]) * wr[k];
                #pragma unroll
                for (int o = 16; o; o >>= 1) s += __shfl_xor_sync(0xffffffffu, s, o);
                if (lane == 0) sc[l] = s;
            }
            __syncthreads();

            float mx = -1e30f;
            for (int l = tid; l < LL; l += 512) mx = fmaxf(mx, sc[l]);
            #pragma unroll
            for (int o = 16; o; o >>= 1) mx = fmaxf(mx, __shfl_xor_sync(0xffffffffu, mx, o));
            if (lane == 0) red[wid] = mx;
            __syncthreads();
            if (wid == 0) {
                float v = (lane < 16) ? red[lane] : -1e30f;
                #pragma unroll
                for (int o = 8; o; o >>= 1) v = fmaxf(v, __shfl_xor_sync(0xffffffffu, v, o));
                if (lane == 0) red[0] = v;
            }
            __syncthreads();
            mx = red[0];
            __syncthreads();

            float sum = 0.f;
            for (int l = tid; l < LL; l += 512) {
                float e = __expf(sc[l] - mx);
                sc[l] = e;
                sum += e;
            }
            #pragma unroll
            for (int o = 16; o; o >>= 1) sum += __shfl_xor_sync(0xffffffffu, sum, o);
            if (lane == 0) red[wid] = sum;
            __syncthreads();
            if (wid == 0) {
                float v = (lane < 16) ? red[lane] : 0.f;
                #pragma unroll
                for (int o = 8; o; o >>= 1) v += __shfl_xor_sync(0xffffffffu, v, o);
                if (lane == 0) red[0] = v;
            }
            __syncthreads();
            float inv = __fdividef(1.f, red[0]);

            bool active = (lengths[b] - 1) > t;
            for (int l = tid; l < LL; l += 512)
                alphas_out[(size_t)b*(TMAX*LL) + (size_t)t*LL + l] = active ? sc[l]*inv : 0.f;

            // z: exactly one f per thread (FF = 512)
            {
                const int f = tid;
                const float* fbb = features + (size_t)b*FL;
                float z0=0.f, z1=0.f, z2=0.f, z3=0.f;
                #pragma unroll 4
                for (int l = 0; l < 196; l += 4) {
                    z0 = fmaf(sc[l+0], __ldg(fbb + (size_t)(l+0)*FF + f), z0);
                    z1 = fmaf(sc[l+1], __ldg(fbb + (size_t)(l+1)*FF + f), z1);
                    z2 = fmaf(sc[l+2], __ldg(fbb + (size_t)(l+2)*FF + f), z2);
                    z3 = fmaf(sc[l+3], __ldg(fbb + (size_t)(l+3)*FF + f), z3);
                }
                float z = (z0 + z1) + (z2 + z3);
                float gate = __ldcg(&g_defb[b*1024 + 512 + f]);
                __stcg(&g_xT[(size_t)(512+f)*64 + b], z * inv * gate);
            }
            // embedding: one e per thread
            {
                int cap = captions[b*TT + t];
                __stcg(&g_xT[(size_t)tid*64 + b], __ldg(&W_emb[(size_t)cap*EE + tid]));
            }
        }
        ep++; grid_bar(ep * NB);

        // ---- P3: gates GEMM + cell; K split across 2 groups of 256 threads --
        {
            const int gp  = tid >> 8;          // K-group 0/1
            const int t8  = tid & 255;
            const int txx = t8 & 15, tyy = t8 >> 4;
            const int kk_a = t8 >> 4, b4 = (t8 & 15) * 4;
            const int cB = t8 >> 2, k4 = (t8 & 3) * 4;
            const int gcol_l = (cB >> 2)*512 + blk*4 + (cB & 3);
            float acc[4] = {0,0,0,0};

            // flattened 96 tiles: [0,64) g_xT/W_ih (K=1024), [64,96) g_hc/W_hh (K=512)
            auto ptrA = [&](int kt) -> const float4* {
                const float* Ab = (kt < 64) ? g_xT : g_hc[p];
                int k0 = (kt < 64) ? kt*16 : (kt-64)*16;
                return reinterpret_cast<const float4*>(Ab + (size_t)(k0 + kk_a)*64 + b4);
            };
            auto ptrW = [&](int kt) -> const float4* {
                const float* Wb = (kt < 64) ? W_ih : W_hh;
                int ws = (kt < 64) ? 1024 : 512;
                int k0 = (kt < 64) ? kt*16 : (kt-64)*16;
                return reinterpret_cast<const float4*>(Wb + (size_t)gcol_l*ws + k0 + k4);
            };

            const int base = gp * 48;
            float4 avp = __ldcg(ptrA(base));
            float4 wvp = make_float4(0,0,0,0);
            if (t8 < 64) wvp = *ptrW(base);
            *reinterpret_cast<float4*>(&As3[gp][0][kk_a][b4]) = avp;
            if (t8 < 64) {
                Bs3[gp][0][k4+0][cB]=wvp.x; Bs3[gp][0][k4+1][cB]=wvp.y;
                Bs3[gp][0][k4+2][cB]=wvp.z; Bs3[gp][0][k4+3][cB]=wvp.w;
            }
            __syncthreads();

            for (int kti = 0; kti < 48; kti++) {
                const int cur = kti & 1;
                const bool more = (kti + 1 < 48);
                if (more) {
                    avp = __ldcg(ptrA(base + kti + 1));
                    if (t8 < 64) wvp = *ptrW(base + kti + 1);
                }
                #pragma unroll
                for (int kk = 0; kk < 16; kk++) {
                    float bval = Bs3[gp][cur][kk][txx];
                    #pragma unroll
                    for (int i = 0; i < 4; i++)
                        acc[i] = fmaf(As3[gp][cur][kk][tyy*4 + i], bval, acc[i]);
                }
                if (more) {
                    const int nxt = cur ^ 1;
                    *reinterpret_cast<float4*>(&As3[gp][nxt][kk_a][b4]) = avp;
                    if (t8 < 64) {
                        Bs3[gp][nxt][k4+0][cB]=wvp.x; Bs3[gp][nxt][k4+1][cB]=wvp.y;
                        Bs3[gp][nxt][k4+2][cB]=wvp.z; Bs3[gp][nxt][k4+3][cB]=wvp.w;
                    }
                }
                __syncthreads();
            }

            if (gp == 0) {
                #pragma unroll
                for (int i = 0; i < 4; i++) gsA[txx][tyy*4 + i] = acc[i];
            } else {
                #pragma unroll
                for (int i = 0; i < 4; i++) gsB[txx][tyy*4 + i] = acc[i];
            }
            __syncthreads();

            // cell update: 256 work items = 64 b x 4 local j
            if (tid < 256) {
                int b  = tid & 63;
                int jl = tid >> 6;
                int j  = blk*4 + jl;
                float gv[4];
                #pragma unroll
                for (int gi = 0; gi < 4; gi++) {
                    int c = gi*4 + jl;
                    int gcol = gi*512 + blk*4 + jl;
                    gv[gi] = gsA[c][b] + gsB[c][b] + b_ih[gcol] + b_hh[gcol];
                }
                float h_old = __ldcg(&g_hc[p][(size_t)j*64 + b]);
                float c_old = __ldcg(&g_hc[p][(size_t)(512+j)*64 + b]);
                float cn = fsigm(gv[1])*c_old + fsigm(gv[0])*ftanh_e(gv[2]);
                float hn = fsigm(gv[3])*ftanh_e(cn);
                g_Hs[(size_t)t*(BB*HH) + b*HH + j] = hn;
                bool act = (lengths[b] - 1) > t;
                __stcg(&g_hc[p^1][(size_t)j*64 + b],       act ? hn : h_old);
                __stcg(&g_hc[p^1][(size_t)(512+j)*64 + b], act ? cn : c_old);
            }
            __syncthreads();
        }
        ep++; grid_bar(ep * NB);
    }
}

// -------------------- host launcher -----------------------------------------
extern "C" void kernel_launch(void* const* d_in, const int* in_sizes, int n_in,
                              void* d_out, int out_size) {
    const float* features = (const float*)d_in[0];
    const int*   captions = (const int*)  d_in[1];
    const int*   lengths  = (const int*)  d_in[2];
    const float* W_emb    = (const float*)d_in[3];
    const float* W_enc    = (const float*)d_in[4];
    const float* b_enc    = (const float*)d_in[5];
    const float* W_dec    = (const float*)d_in[6];
    const float* b_dec    = (const float*)d_in[7];
    const float* W_full   = (const float*)d_in[8];
    /* b_full (d_in[9]) softmax-invariant: unused */
    const float* W_fbeta  = (const float*)d_in[10];
    const float* b_fbeta  = (const float*)d_in[11];
    const float* W_ih     = (const float*)d_in[12];
    const float* W_hh     = (const float*)d_in[13];
    const float* b_ih     = (const float*)d_in[14];
    const float* b_hh     = (const float*)d_in[15];
    const float* W_out    = (const float*)d_in[16];
    const float* b_out    = (const float*)d_in[17];
    const float* W_init_h = (const float*)d_in[18];
    const float* b_init_h = (const float*)d_in[19];
    const float* W_init_c = (const float*)d_in[20];
    const float* b_init_c = (const float*)d_in[21];

    float* out = (float*)d_out;
    float* alphas_out = out + (size_t)BB*TMAX*VV;

    (void)n_in; (void)in_sizes; (void)out_size;

    // device address of g_enatt for the generic GEMM (host symbol != device addr!)
    float* p_enatt;
    cudaGetSymbolAddress((void**)&p_enatt, g_enatt);

    // #0: merged setup (Winit/binit/g_bar reset + feature mean)
    setup_init<<<6144, 256>>>(W_init_h, b_init_h, W_init_c, b_init_c, features);

    // #1: [h0|c0] init GEMM (transposed)
    gemm_init<<<16, 256>>>();

    // #2: en_att = feat_r @ W_enc^T + b_enc   (M=12544, N=512, K=512)
    {
        dim3 g(AA/GBN, ENATT_M/GBM);   // (4, 98)
        gemm128<<<g, 256>>>(features, W_enc, b_enc, p_enatt, ENATT_M, AA, FF);
    }

    // #3: whole recurrence in ONE persistent kernel (positioned for ncu capture)
    recurrence<<<NB, 512>>>(features, W_dec, b_dec, W_fbeta, b_fbeta, W_full,
                            W_emb, captions, lengths, W_ih, W_hh, b_ih, b_hh,
                            alphas_out);

    // #4/#5: ragged-row bookkeeping for preds (only preds depends on these)
    setup_rowmap<<<1, 256>>>(lengths);
    zero_inactive<<<TMAX*BB, 256>>>(lengths, out);

    // #6: compacted output projection (active rows only)
    {
        dim3 g((VV + GBN - 1)/GBN, (TMAX*BB + GBM - 1)/GBM);  // (79, 16)
        gemm_preds_c<<<g, 256>>>(W_out, b_out, out);
    }
}